// round 14
// baseline (speedup 1.0000x reference)
#include <cuda_runtime.h>
#include <cuda_fp16.h>
#include <math.h>
#include <cstdint>

// Problem constants
constexpr int Bb = 2;
constexpr int T  = 2048;
constexpr int C  = 1024;
constexpr int Hh = 16;
constexpr int Dd = 64;
constexpr int M  = Bb * T;       // 4096 tokens
constexpr int FF = 4 * C;        // 4096
constexpr int GSK = 296;         // stream-K grid: 2 CTAs x 148 SMs (all co-resident)
constexpr int MAXTILES = 1024;

// ---------------- scratch (static device memory; no allocation) -------------
__device__ __half g_h  [M * C];
__device__ __half g_qkv[(size_t)3 * M * C];
__device__ __half g_y  [M * C];
__device__ float  g_x1 [M * C];
__device__ __half g_hid[(size_t)M * FF];
__device__ __half g_wtqkv[(size_t)3 * C * C];
__device__ float  g_bqkv [3 * C];
__device__ __half g_wto[C * C];
__device__ __half g_wt1[(size_t)C * FF];
__device__ __half g_wt2[(size_t)C * FF];
// stream-K workspace: 2 partial slots per tile, 128x128 fp32 each
__device__ float  g_ws[(size_t)MAXTILES * 2 * 128 * 128];
__device__ int    g_flags[MAXTILES];

// ---------------- side stream + events ---------------------------------------
struct PrepStreams {
    cudaStream_t s1;
    cudaEvent_t e0, e1, e2;
    PrepStreams() {
        int least = 0, greatest = 0;
        cudaDeviceGetStreamPriorityRange(&least, &greatest);
        cudaStreamCreateWithPriority(&s1, cudaStreamNonBlocking, least);
        cudaEventCreateWithFlags(&e0, cudaEventDisableTiming);
        cudaEventCreateWithFlags(&e1, cudaEventDisableTiming);
        cudaEventCreateWithFlags(&e2, cudaEventDisableTiming);
    }
};
static PrepStreams g_ps;

// ---------------- helpers ----------------------------------------------------
__device__ __forceinline__ uint32_t smem_u32(const void* p) {
    uint32_t a;
    asm("{ .reg .u64 t; cvta.to.shared.u64 t, %1; cvt.u32.u64 %0, t; }"
        : "=r"(a) : "l"(p));
    return a;
}
__device__ __forceinline__ void cp_async16(uint32_t dst, const void* src) {
    asm volatile("cp.async.cg.shared.global [%0], [%1], 16;"
                 :: "r"(dst), "l"(src) : "memory");
}
#define CP_COMMIT() asm volatile("cp.async.commit_group;" ::: "memory")
#define CP_WAIT(n)  asm volatile("cp.async.wait_group %0;" :: "n"(n) : "memory")

__device__ __forceinline__ void mma_f16(float* c, const uint32_t* a, const uint32_t* b) {
    asm volatile(
        "mma.sync.aligned.m16n8k16.row.col.f32.f16.f16.f32 "
        "{%0,%1,%2,%3}, {%4,%5,%6,%7}, {%8,%9}, {%0,%1,%2,%3};"
        : "+f"(c[0]), "+f"(c[1]), "+f"(c[2]), "+f"(c[3])
        : "r"(a[0]), "r"(a[1]), "r"(a[2]), "r"(a[3]), "r"(b[0]), "r"(b[1]));
}
__device__ __forceinline__ void ldm_x4(uint32_t* r, uint32_t addr) {
    asm volatile("ldmatrix.sync.aligned.m8n8.x4.shared.b16 {%0,%1,%2,%3}, [%4];"
        : "=r"(r[0]), "=r"(r[1]), "=r"(r[2]), "=r"(r[3]) : "r"(addr));
}
__device__ __forceinline__ void ldm_x4_t(uint32_t* r, uint32_t addr) {
    asm volatile("ldmatrix.sync.aligned.m8n8.x4.trans.shared.b16 {%0,%1,%2,%3}, [%4];"
        : "=r"(r[0]), "=r"(r[1]), "=r"(r[2]), "=r"(r[3]) : "r"(addr));
}
__device__ __forceinline__ uint32_t packh2(float a, float b) {
    __half2 h = __floats2half2_rn(a, b);
    return *(uint32_t*)&h;
}
__device__ __forceinline__ float4 ldcg4(const float* p) {
    float4 v;
    asm volatile("ld.global.cg.v4.f32 {%0,%1,%2,%3}, [%4];"
        : "=f"(v.x), "=f"(v.y), "=f"(v.z), "=f"(v.w) : "l"(p));
    return v;
}

// ---------------- stream-K fp16 GEMM, 128x128 tiles, 296 persistent CTAs -----
// EPI: 0 = fused-QKV head-scatter (+log2e/8 on Q), 1 = residual add fp32, 2 = GELU -> fp16
constexpr int LDKH = 40;                   // halfs per smem row (80 B)
constexpr int TILE_H = 128 * LDKH;
constexpr int SMEM_G = 3 * 2 * TILE_H * 2; // 61440 B

template<int EPI>
__global__ __launch_bounds__(256, 2)
void gemm_sk(const __half* __restrict__ A,     // [M,K] row-major fp16
             const __half* __restrict__ Bt,    // [N,K] row-major fp16
             const float* __restrict__ bias,   // [N]
             const float* __restrict__ resid,  // [M,N] (EPI==1)
             void* __restrict__ outv,
             int Nn, int Kk)
{
    extern __shared__ __half smh[];
    const uint32_t sb = smem_u32(smh);
    const int tid  = threadIdx.x;
    const int wid  = tid >> 5;
    const int lane = tid & 31;
    const int qr   = lane >> 2;
    const int qc   = lane & 3;
    const int warp_m = (wid & 1) * 64;
    const int warp_n = (wid >> 1) * 32;

    const int lane15 = lane & 15;
    const int lanehi = lane >> 4;
    const int bl8    = lane & 7;
    const int blg    = lane >> 3;

    const int NT = Nn >> 7;            // N tiles
    const int KT = Kk >> 5;            // K chunks per tile
    const int U  = NT * (M >> 7) * KT; // total work units
    const int base = U / GSK, rem = U % GSK;
    const int g = blockIdx.x;
    int u        = g * base + (g < rem ? g : rem);
    const int u1 = u + base + (g < rem ? 1 : 0);

    auto cta_of = [&](int uu) {
        const int thr = (base + 1) * rem;
        return (uu < thr) ? uu / (base + 1) : rem + (uu - thr) / base;
    };

    #pragma unroll 1
    while (u < u1) {
        const int t   = u / KT;
        const int c0  = u - t * KT;
        const int run = min(KT - c0, u1 - u);
        const int c1  = c0 + run;
        const int bn  = (t % NT) << 7;
        const int bm  = (t / NT) << 7;

        auto issue = [&](int kt) {
            const int buf = kt % 3;
            const int k0  = kt * 32;
            const uint32_t ao = sb + (uint32_t)(2 * buf * TILE_H) * 2;
            const uint32_t bo = ao + TILE_H * 2;
            #pragma unroll
            for (int i = 0; i < 2; i++) {
                int idx = i * 256 + tid;
                int r = idx >> 2, c = idx & 3;
                cp_async16(ao + r * 80 + c * 16, &A[(size_t)(bm + r) * Kk + k0 + c * 8]);
            }
            #pragma unroll
            for (int i = 0; i < 2; i++) {
                int idx = i * 256 + tid;
                int r = idx >> 2, c = idx & 3;
                cp_async16(bo + r * 80 + c * 16, &Bt[(size_t)(bn + r) * Kk + k0 + c * 8]);
            }
            CP_COMMIT();
        };

        float acc[4][4][4] = {};
        float* accL = &acc[0][0][0];

        issue(c0);
        if (run > 1) issue(c0 + 1); else CP_COMMIT();

        #pragma unroll 1
        for (int kt = c0; kt < c1; kt++) {
            CP_WAIT(1);
            __syncthreads();
            if (kt + 2 < c1) issue(kt + 2); else CP_COMMIT();

            const uint32_t ao = sb + (uint32_t)(2 * (kt % 3) * TILE_H) * 2;
            const uint32_t bo = ao + TILE_H * 2;

            uint32_t bfr[4][4];
            #pragma unroll
            for (int jn = 0; jn < 4; jn++)
                ldm_x4(bfr[jn], bo + (uint32_t)(warp_n + jn * 8 + bl8) * 80 + blg * 16);

            #pragma unroll
            for (int ks = 0; ks < 2; ks++) {
                uint32_t a[4][4];
                #pragma unroll
                for (int im = 0; im < 4; im++)
                    ldm_x4(a[im], ao + (uint32_t)(warp_m + im * 16 + lane15) * 80
                                  + ks * 32 + lanehi * 16);
                #pragma unroll
                for (int im = 0; im < 4; im++)
                    #pragma unroll
                    for (int jn = 0; jn < 4; jn++)
                        mma_f16(acc[im][jn], a[im], &bfr[jn][ks * 2]);
            }
            // NO bottom barrier: issue(kt+2) targets the buffer consumed at kt-1,
            // and every warp passed this iteration's top barrier after finishing kt-1.
        }

        if (c0 != 0) {
            // non-owner contributor: spill partial, signal
            const int o   = cta_of(t * KT);
            const int ord = g - o;                       // 1 or 2
            float* slot = g_ws + ((size_t)t * 2 + (ord - 1)) * (128 * 128) + (size_t)tid * 64;
            #pragma unroll
            for (int i = 0; i < 16; i++)
                *(float4*)(slot + 4 * i) =
                    make_float4(accL[4*i], accL[4*i+1], accL[4*i+2], accL[4*i+3]);
            __threadfence();
            __syncthreads();
            if (tid == 0) atomicAdd(&g_flags[t], run);
        } else {
            if (c1 < KT) {
                // owner of a split tile: wait for the other contributors
                const int last   = cta_of(t * KT + KT - 1);
                const int nslots = last - g;             // 1 or 2
                if (tid == 0) {
                    const int need = KT - run;
                    while (*(volatile int*)&g_flags[t] != need) __nanosleep(64);
                    __threadfence();
                }
                __syncthreads();
                for (int s = 0; s < nslots; s++) {
                    const float* p = g_ws + ((size_t)t * 2 + s) * (128 * 128) + (size_t)tid * 64;
                    #pragma unroll
                    for (int i = 0; i < 16; i++) {
                        float4 v = ldcg4(p + 4 * i);
                        accL[4*i]   += v.x; accL[4*i+1] += v.y;
                        accL[4*i+2] += v.z; accL[4*i+3] += v.w;
                    }
                }
            }
            // epilogue (owner writes final output)
            #pragma unroll
            for (int im = 0; im < 4; im++) {
                const int r0 = bm + warp_m + im * 16 + qr;
                const int r1 = r0 + 8;
                #pragma unroll
                for (int jn = 0; jn < 4; jn++) {
                    const int cc0 = bn + warp_n + jn * 8 + qc * 2;
                    const float2 bv = *(const float2*)&bias[cc0];
                    float2 v0, v1;
                    v0.x = acc[im][jn][0] + bv.x;
                    v0.y = acc[im][jn][1] + bv.y;
                    v1.x = acc[im][jn][2] + bv.x;
                    v1.y = acc[im][jn][3] + bv.y;
                    if (EPI == 2) {
                        v0.x = 0.5f * v0.x * (1.0f + erff(v0.x * 0.70710678118654752f));
                        v0.y = 0.5f * v0.y * (1.0f + erff(v0.y * 0.70710678118654752f));
                        v1.x = 0.5f * v1.x * (1.0f + erff(v1.x * 0.70710678118654752f));
                        v1.y = 0.5f * v1.y * (1.0f + erff(v1.y * 0.70710678118654752f));
                        __half* out = (__half*)outv;
                        *(__half2*)&out[(size_t)r0 * Nn + cc0] = __floats2half2_rn(v0.x, v0.y);
                        *(__half2*)&out[(size_t)r1 * Nn + cc0] = __floats2half2_rn(v1.x, v1.y);
                    } else if (EPI == 1) {
                        const float2 q0 = *(const float2*)&resid[(size_t)r0 * Nn + cc0];
                        const float2 q1 = *(const float2*)&resid[(size_t)r1 * Nn + cc0];
                        float* out = (float*)outv;
                        v0.x += q0.x; v0.y += q0.y;
                        v1.x += q1.x; v1.y += q1.y;
                        *(float2*)&out[(size_t)r0 * Nn + cc0] = v0;
                        *(float2*)&out[(size_t)r1 * Nn + cc0] = v1;
                    } else {
                        const int mat = cc0 >> 10;
                        if (mat == 0) {
                            constexpr float QS = 0.125f * 1.4426950408889634f;
                            v0.x *= QS; v0.y *= QS;
                            v1.x *= QS; v1.y *= QS;
                        }
                        const int cc = cc0 & 1023;
                        const int hi = cc >> 6, dd = cc & 63;
                        __half* ob = (__half*)outv + (size_t)mat * M * C;
                        {
                            const int bi = r0 >> 11, tt = r0 & 2047;
                            *(__half2*)&ob[(((size_t)(bi * Hh + hi)) * T + tt) * Dd + dd] =
                                __floats2half2_rn(v0.x, v0.y);
                        }
                        {
                            const int bi = r1 >> 11, tt = r1 & 2047;
                            *(__half2*)&ob[(((size_t)(bi * Hh + hi)) * T + tt) * Dd + dd] =
                                __floats2half2_rn(v1.x, v1.y);
                        }
                    }
                }
            }
        }
        __syncthreads();   // per-TILE barrier: next tile's prologue overwrites smem
        u += run;
    }
}

// ---------------- fp16 flash attention (unchanged, known-good) ---------------
constexpr int LDAH = 72;
constexpr int SK0_H = 64 * LDAH;
constexpr int SV0_H = 3 * 64 * LDAH;
constexpr int SMEM_ATT = 5 * 64 * LDAH * 2;  // 46080 B

__global__ __launch_bounds__(128)
void attn_mma(const __half* __restrict__ Q,
              const __half* __restrict__ K,
              const __half* __restrict__ V,
              __half* __restrict__ Y)
{
    extern __shared__ __half smh[];
    const uint32_t sb = smem_u32(smh);
    const int tid  = threadIdx.x;
    const int wid  = tid >> 5;
    const int lane = tid & 31;
    const int qr   = lane >> 2;
    const int qc   = lane & 3;
    const int lane15 = lane & 15;
    const int lanehi = lane >> 4;
    const int bl8    = lane & 7;
    const int blg    = lane >> 3;

    const int bh = blockIdx.y;
    const int qb = (int)gridDim.x - 1 - (int)blockIdx.x;

    const __half* Qp = Q + (size_t)bh * T * Dd + (size_t)qb * 64 * Dd;
    const __half* Kp = K + (size_t)bh * T * Dd;
    const __half* Vp = V + (size_t)bh * T * Dd;

    #pragma unroll
    for (int i = 0; i < 4; i++) {
        int idx = i * 128 + tid;
        int r = idx >> 3, c = idx & 7;
        *(float4*)((char*)smh + r * 144 + c * 16) = *(const float4*)&Qp[r * 64 + c * 8];
    }

    auto issue_kv = [&](int buf, int kt) {
        const uint32_t kb = sb + (uint32_t)(SK0_H + buf * 64 * LDAH) * 2;
        const uint32_t vb = sb + (uint32_t)(SV0_H + buf * 64 * LDAH) * 2;
        const __half* Ks = Kp + (size_t)kt * 64 * 64;
        const __half* Vs = Vp + (size_t)kt * 64 * 64;
        #pragma unroll
        for (int i = 0; i < 4; i++) {
            int idx = i * 128 + tid;
            int r = idx >> 3, c = idx & 7;
            cp_async16(kb + r * 144 + c * 16, Ks + r * 64 + c * 8);
        }
        #pragma unroll
        for (int i = 0; i < 4; i++) {
            int idx = i * 128 + tid;
            int r = idx >> 3, c = idx & 7;
            cp_async16(vb + r * 144 + c * 16, Vs + r * 64 + c * 8);
        }
        CP_COMMIT();
    };

    issue_kv(0, 0);
    __syncthreads();

    uint32_t qf[4][4];
    #pragma unroll
    for (int kc = 0; kc < 4; kc++)
        ldm_x4(qf[kc], sb + (uint32_t)(wid * 16 + lane15) * 144 + kc * 32 + lanehi * 16);

    float o[8][4] = {};
    float m0 = -1e30f, m1 = -1e30f, l0 = 0.0f, l1 = 0.0f;

    for (int kt = 0; kt <= qb; kt++) {
        const int cur = kt & 1;
        if (kt < qb) issue_kv(1 - cur, kt + 1);
        if (kt < qb) { CP_WAIT(1); } else { CP_WAIT(0); }
        __syncthreads();

        const uint32_t kb = sb + (uint32_t)(SK0_H + cur * 64 * LDAH) * 2;
        const uint32_t vb = sb + (uint32_t)(SV0_H + cur * 64 * LDAH) * 2;

        float sacc[8][4];
        #pragma unroll
        for (int jb = 0; jb < 8; jb++) {
            sacc[jb][0] = sacc[jb][1] = sacc[jb][2] = sacc[jb][3] = 0.0f;
            uint32_t r1[4], r2[4];
            ldm_x4(r1, kb + (uint32_t)(jb * 8 + bl8) * 144 + blg * 16);
            ldm_x4(r2, kb + (uint32_t)(jb * 8 + bl8) * 144 + blg * 16 + 64);
            mma_f16(sacc[jb], qf[0], &r1[0]);
            mma_f16(sacc[jb], qf[1], &r1[2]);
            mma_f16(sacc[jb], qf[2], &r2[0]);
            mma_f16(sacc[jb], qf[3], &r2[2]);
        }

        if (kt == qb) {
            const int row0 = wid * 16 + qr;
            const int row1 = row0 + 8;
            #pragma unroll
            for (int jb = 0; jb < 8; jb++) {
                const int cb = jb * 8 + 2 * qc;
                if (cb     > row0) sacc[jb][0] = -1e30f;
                if (cb + 1 > row0) sacc[jb][1] = -1e30f;
                if (cb     > row1) sacc[jb][2] = -1e30f;
                if (cb + 1 > row1) sacc[jb][3] = -1e30f;
            }
        }

        float r0 = -1e30f, r1 = -1e30f;
        #pragma unroll
        for (int jb = 0; jb < 8; jb++) {
            r0 = fmaxf(r0, fmaxf(sacc[jb][0], sacc[jb][1]));
            r1 = fmaxf(r1, fmaxf(sacc[jb][2], sacc[jb][3]));
        }
        r0 = fmaxf(r0, __shfl_xor_sync(0xffffffffu, r0, 1));
        r0 = fmaxf(r0, __shfl_xor_sync(0xffffffffu, r0, 2));
        r1 = fmaxf(r1, __shfl_xor_sync(0xffffffffu, r1, 1));
        r1 = fmaxf(r1, __shfl_xor_sync(0xffffffffu, r1, 2));

        const float mn0 = fmaxf(m0, r0), mn1 = fmaxf(m1, r1);
        const float cr0 = exp2f(m0 - mn0), cr1 = exp2f(m1 - mn1);
        m0 = mn0; m1 = mn1;
        l0 *= cr0; l1 *= cr1;
        #pragma unroll
        for (int db = 0; db < 8; db++) {
            o[db][0] *= cr0; o[db][1] *= cr0;
            o[db][2] *= cr1; o[db][3] *= cr1;
        }

        uint32_t pf[4][4];
        #pragma unroll
        for (int jb = 0; jb < 8; jb++) {
            float p0 = exp2f(sacc[jb][0] - m0);
            float p1 = exp2f(sacc[jb][1] - m0);
            float p2 = exp2f(sacc[jb][2] - m1);
            float p3 = exp2f(sacc[jb][3] - m1);
            l0 += p0 + p1; l1 += p2 + p3;
            const int kc = jb >> 1;
            const int hh = (jb & 1) * 2;
            pf[kc][hh]     = packh2(p0, p1);
            pf[kc][hh + 1] = packh2(p2, p3);
        }

        #pragma unroll
        for (int dn = 0; dn < 8; dn++) {
            uint32_t v1[4], v2[4];
            ldm_x4_t(v1, vb + (uint32_t)lane * 144 + dn * 16);
            ldm_x4_t(v2, vb + (uint32_t)(32 + lane) * 144 + dn * 16);
            mma_f16(o[dn], pf[0], &v1[0]);
            mma_f16(o[dn], pf[1], &v1[2]);
            mma_f16(o[dn], pf[2], &v2[0]);
            mma_f16(o[dn], pf[3], &v2[2]);
        }
        if (kt < qb) __syncthreads();
    }

    l0 += __shfl_xor_sync(0xffffffffu, l0, 1);
    l0 += __shfl_xor_sync(0xffffffffu, l0, 2);
    l1 += __shfl_xor_sync(0xffffffffu, l1, 1);
    l1 += __shfl_xor_sync(0xffffffffu, l1, 2);
    const float inv0 = 1.0f / l0, inv1 = 1.0f / l1;

    const int bi = bh >> 4, hi = bh & 15;
    const int q0 = qb * 64 + wid * 16 + qr;
    const int q1 = q0 + 8;
    __half* y0 = Y + ((size_t)(bi * T + q0)) * C + hi * Dd;
    __half* y1 = Y + ((size_t)(bi * T + q1)) * C + hi * Dd;
    #pragma unroll
    for (int dn = 0; dn < 8; dn++) {
        const int d = dn * 8 + 2 * qc;
        *(__half2*)&y0[d] = __floats2half2_rn(o[dn][0] * inv0, o[dn][1] * inv0);
        *(__half2*)&y1[d] = __floats2half2_rn(o[dn][2] * inv1, o[dn][3] * inv1);
    }
}

// ---------------- QKV weight transpose -> fp16 [N][K] (+ bias pack) ----------
__global__ void transpose_qkv(const float* __restrict__ wq, const float* __restrict__ wk,
                              const float* __restrict__ wv,
                              __half* __restrict__ oq, __half* __restrict__ ok,
                              __half* __restrict__ ov,
                              const float* __restrict__ bq, const float* __restrict__ bk,
                              const float* __restrict__ bv, float* __restrict__ bqkv)
{
    __shared__ float tile[32][33];
    const int z = blockIdx.z;
    const float* in = (z == 0) ? wq : (z == 1) ? wk : wv;
    __half* out = (z == 0) ? oq : (z == 1) ? ok : ov;
    int x = blockIdx.x * 32 + threadIdx.x;
    int y = blockIdx.y * 32 + threadIdx.y;
    #pragma unroll
    for (int j = 0; j < 32; j += 8)
        tile[threadIdx.y + j][threadIdx.x] = in[(size_t)(y + j) * C + x];
    __syncthreads();
    int xo = blockIdx.y * 32 + threadIdx.x;
    int yo = blockIdx.x * 32 + threadIdx.y;
    #pragma unroll
    for (int j = 0; j < 32; j += 8)
        out[(size_t)(yo + j) * C + xo] = __float2half_rn(tile[threadIdx.x][threadIdx.y + j]);

    if (z == 2 && blockIdx.x == 0 && blockIdx.y == 0) {
        int t = threadIdx.y * 32 + threadIdx.x;
        for (int i = t; i < 3 * C; i += 256) {
            const float* src = (i < C) ? bq : (i < 2 * C) ? bk : bv;
            bqkv[i] = src[i & (C - 1)];
        }
    }
}

__global__ void transpose_h(const float* __restrict__ in, __half* __restrict__ out,
                            int R, int Cc)
{
    __shared__ float tile[32][33];
    int x = blockIdx.x * 32 + threadIdx.x;
    int y = blockIdx.y * 32 + threadIdx.y;
    #pragma unroll
    for (int j = 0; j < 32; j += 8)
        tile[threadIdx.y + j][threadIdx.x] = in[(size_t)(y + j) * Cc + x];
    __syncthreads();
    int xo = blockIdx.y * 32 + threadIdx.x;
    int yo = blockIdx.x * 32 + threadIdx.y;
    #pragma unroll
    for (int j = 0; j < 32; j += 8)
        out[(size_t)(yo + j) * R + xo] = __float2half_rn(tile[threadIdx.x][threadIdx.y + j]);
}

// ---------------- LayerNorm: warp-per-row, fp16 row cache --------------------
__global__ __launch_bounds__(512)
void ln_kernel(const float* __restrict__ X,
               const float* __restrict__ w,
               const float* __restrict__ b,
               __half* __restrict__ out)
{
    const int lane = threadIdx.x & 31;
    const int row  = blockIdx.x * 16 + (threadIdx.x >> 5);
    const float* xr = X + (size_t)row * C;

    __half2 xh[16];
    float s = 0.0f, sq = 0.0f;
    #pragma unroll
    for (int i = 0; i < 8; i++) {
        const float4 v = *(const float4*)&xr[(i * 32 + lane) * 4];
        s  += v.x + v.y + v.z + v.w;
        sq += v.x*v.x + v.y*v.y + v.z*v.z + v.w*v.w;
        xh[2*i]     = __floats2half2_rn(v.x, v.y);
        xh[2*i + 1] = __floats2half2_rn(v.z, v.w);
    }
    #pragma unroll
    for (int off = 16; off > 0; off >>= 1) {
        s  += __shfl_xor_sync(0xffffffffu, s,  off);
        sq += __shfl_xor_sync(0xffffffffu, sq, off);
    }
    const float mu = s * (1.0f / C);
    const float r  = rsqrtf(sq * (1.0f / C) - mu * mu + 1e-5f);

    __half* orow = out + (size_t)row * C;
    #pragma unroll
    for (int i = 0; i < 8; i++) {
        const int c = (i * 32 + lane) * 4;
        const float4 wv = *(const float4*)&w[c];
        const float4 bv = *(const float4*)&b[c];
        const float2 a0 = __half22float2(xh[2*i]);
        const float2 a1 = __half22float2(xh[2*i + 1]);
        __half2 h0 = __floats2half2_rn((a0.x - mu) * r * wv.x + bv.x,
                                       (a0.y - mu) * r * wv.y + bv.y);
        __half2 h1 = __floats2half2_rn((a1.x - mu) * r * wv.z + bv.z,
                                       (a1.y - mu) * r * wv.w + bv.w);
        *(__half2*)&orow[c]     = h0;
        *(__half2*)&orow[c + 2] = h1;
    }
}

// ---------------- launcher ----------------------------------------------------
extern "C" void kernel_launch(void* const* d_in, const int* in_sizes, int n_in,
                              void* d_out, int out_size)
{
    const float* x     = (const float*)d_in[0];
    const float* ln1_w = (const float*)d_in[1];
    const float* ln1_b = (const float*)d_in[2];
    const float* wq    = (const float*)d_in[3];
    const float* bq    = (const float*)d_in[4];
    const float* wk    = (const float*)d_in[5];
    const float* bk    = (const float*)d_in[6];
    const float* wv    = (const float*)d_in[7];
    const float* bv    = (const float*)d_in[8];
    const float* wo    = (const float*)d_in[9];
    const float* bo    = (const float*)d_in[10];
    const float* ln2_w = (const float*)d_in[11];
    const float* ln2_b = (const float*)d_in[12];
    const float* w1    = (const float*)d_in[13];
    const float* b1    = (const float*)d_in[14];
    const float* w2    = (const float*)d_in[15];
    const float* b2    = (const float*)d_in[16];

    __half *h, *qkv, *y, *hid, *wtqkv, *wto, *wt1, *wt2;
    float *x1, *bqkv;
    int* flags;
    cudaGetSymbolAddress((void**)&h,     g_h);
    cudaGetSymbolAddress((void**)&qkv,   g_qkv);
    cudaGetSymbolAddress((void**)&y,     g_y);
    cudaGetSymbolAddress((void**)&x1,    g_x1);
    cudaGetSymbolAddress((void**)&hid,   g_hid);
    cudaGetSymbolAddress((void**)&wtqkv, g_wtqkv);
    cudaGetSymbolAddress((void**)&bqkv,  g_bqkv);
    cudaGetSymbolAddress((void**)&wto,   g_wto);
    cudaGetSymbolAddress((void**)&wt1,   g_wt1);
    cudaGetSymbolAddress((void**)&wt2,   g_wt2);
    cudaGetSymbolAddress((void**)&flags, g_flags);

    float* out = (float*)d_out;
    __half* q = qkv;
    __half* k = qkv + (size_t)M * C;
    __half* v = qkv + (size_t)2 * M * C;

    cudaFuncSetAttribute(gemm_sk<0>, cudaFuncAttributeMaxDynamicSharedMemorySize, SMEM_G);
    cudaFuncSetAttribute(gemm_sk<1>, cudaFuncAttributeMaxDynamicSharedMemorySize, SMEM_G);
    cudaFuncSetAttribute(gemm_sk<2>, cudaFuncAttributeMaxDynamicSharedMemorySize, SMEM_G);
    cudaFuncSetAttribute(attn_mma,   cudaFuncAttributeMaxDynamicSharedMemorySize, SMEM_ATT);

    // fork low-priority side stream for weight prep
    cudaEventRecord(g_ps.e0, 0);
    cudaStreamWaitEvent(g_ps.s1, g_ps.e0, 0);

    dim3 tb(32, 8);
    transpose_qkv<<<dim3(C/32, C/32, 3), tb, 0, g_ps.s1>>>(
        wq, wk, wv, wtqkv, wtqkv + C * C, wtqkv + 2 * C * C, bq, bk, bv, bqkv);
    cudaEventRecord(g_ps.e1, g_ps.s1);
    transpose_h<<<dim3(C/32,  C/32),  tb, 0, g_ps.s1>>>(wo, wto, C,  C);
    transpose_h<<<dim3(FF/32, C/32),  tb, 0, g_ps.s1>>>(w1, wt1, C,  FF);
    transpose_h<<<dim3(C/32,  FF/32), tb, 0, g_ps.s1>>>(w2, wt2, FF, C);
    cudaEventRecord(g_ps.e2, g_ps.s1);

    // main stream
    ln_kernel<<<M / 16, 512>>>(x, ln1_w, ln1_b, h);
    cudaStreamWaitEvent(0, g_ps.e1, 0);
    cudaMemsetAsync(flags, 0, (3*C/128) * (M/128) * sizeof(int), 0);      // 768 tiles
    gemm_sk<0><<<GSK, 256, SMEM_G>>>(h, wtqkv, bqkv, nullptr, qkv, 3*C, C);
    cudaStreamWaitEvent(0, g_ps.e2, 0);
    attn_mma<<<dim3(T/64, Bb*Hh), 128, SMEM_ATT>>>(q, k, v, y);
    cudaMemsetAsync(flags, 0, (C/128) * (M/128) * sizeof(int), 0);        // 256 tiles
    gemm_sk<1><<<GSK, 256, SMEM_G>>>(y, wto, bo, x, x1, C, C);
    ln_kernel<<<M / 16, 512>>>(x1, ln2_w, ln2_b, h);
    cudaMemsetAsync(flags, 0, (FF/128) * (M/128) * sizeof(int), 0);       // 1024 tiles
    gemm_sk<2><<<GSK, 256, SMEM_G>>>(h, wt1, b1, nullptr, hid, FF, C);
    cudaMemsetAsync(flags, 0, (C/128) * (M/128) * sizeof(int), 0);        // 256 tiles
    gemm_sk<1><<<GSK, 256, SMEM_G>>>(hid, wt2, b2, x1, out, C, FF);
}

// round 15
// speedup vs baseline: 1.6576x; 1.6576x over previous
#include <cuda_runtime.h>
#include <cuda_fp16.h>
#include <math.h>
#include <cstdint>

// Problem constants
constexpr int Bb = 2;
constexpr int T  = 2048;
constexpr int C  = 1024;
constexpr int Hh = 16;
constexpr int Dd = 64;
constexpr int M  = Bb * T;       // 4096 tokens
constexpr int FF = 4 * C;        // 4096

// ---------------- scratch (static device memory; no allocation) -------------
__device__ __half g_h  [M * C];             // LN output (fp16)
__device__ __half g_qkv[(size_t)3 * M * C]; // q|k|v head layout; q pre-scaled by log2e/8
__device__ __half g_y  [M * C];             // attn out (fp16)
__device__ float  g_x1 [M * C];             // residual stream (fp32)
__device__ __half g_hid[(size_t)M * FF];    // MLP hidden (fp16)
// transposed weights, [N][K] layout, fp16
__device__ __half g_wtqkv[(size_t)3 * C * C];
__device__ float  g_bqkv [3 * C];
__device__ __half g_wto[C * C];
__device__ __half g_wt1[(size_t)C * FF];
__device__ __half g_wt2[(size_t)C * FF];

// ---------------- side stream + events (created before harness checkpoints) --
struct PrepStreams {
    cudaStream_t s1;
    cudaEvent_t e0, e1, e2;
    PrepStreams() {
        int least = 0, greatest = 0;
        cudaDeviceGetStreamPriorityRange(&least, &greatest);
        cudaStreamCreateWithPriority(&s1, cudaStreamNonBlocking, least);  // lowest prio
        cudaEventCreateWithFlags(&e0, cudaEventDisableTiming);
        cudaEventCreateWithFlags(&e1, cudaEventDisableTiming);
        cudaEventCreateWithFlags(&e2, cudaEventDisableTiming);
    }
};
static PrepStreams g_ps;

// ---------------- helpers ----------------------------------------------------
__device__ __forceinline__ uint32_t smem_u32(const void* p) {
    uint32_t a;
    asm("{ .reg .u64 t; cvta.to.shared.u64 t, %1; cvt.u32.u64 %0, t; }"
        : "=r"(a) : "l"(p));
    return a;
}
__device__ __forceinline__ void cp_async16(uint32_t dst, const void* src) {
    asm volatile("cp.async.cg.shared.global [%0], [%1], 16;"
                 :: "r"(dst), "l"(src) : "memory");
}
#define CP_COMMIT() asm volatile("cp.async.commit_group;" ::: "memory")
#define CP_WAIT(n)  asm volatile("cp.async.wait_group %0;" :: "n"(n) : "memory")

__device__ __forceinline__ void mma_f16(float* c, const uint32_t* a, const uint32_t* b) {
    asm volatile(
        "mma.sync.aligned.m16n8k16.row.col.f32.f16.f16.f32 "
        "{%0,%1,%2,%3}, {%4,%5,%6,%7}, {%8,%9}, {%0,%1,%2,%3};"
        : "+f"(c[0]), "+f"(c[1]), "+f"(c[2]), "+f"(c[3])
        : "r"(a[0]), "r"(a[1]), "r"(a[2]), "r"(a[3]), "r"(b[0]), "r"(b[1]));
}
__device__ __forceinline__ void ldm_x4(uint32_t* r, uint32_t addr) {
    asm volatile("ldmatrix.sync.aligned.m8n8.x4.shared.b16 {%0,%1,%2,%3}, [%4];"
        : "=r"(r[0]), "=r"(r[1]), "=r"(r[2]), "=r"(r[3]) : "r"(addr));
}
__device__ __forceinline__ void ldm_x4_t(uint32_t* r, uint32_t addr) {
    asm volatile("ldmatrix.sync.aligned.m8n8.x4.trans.shared.b16 {%0,%1,%2,%3}, [%4];"
        : "=r"(r[0]), "=r"(r[1]), "=r"(r[2]), "=r"(r[3]) : "r"(addr));
}
__device__ __forceinline__ uint32_t packh2(float a, float b) {
    __half2 h = __floats2half2_rn(a, b);
    return *(uint32_t*)&h;
}

// ---------------- fp16 mma.sync GEMM, 128x128x32, 3-stage, 2 CTA/SM ---------
// EPI: 0 = fused-QKV head-scatter (+log2e/8 on Q), 1 = residual add fp32, 2 = GELU -> fp16
constexpr int LDKH = 40;                   // halfs per smem row (80 B)
constexpr int TILE_H = 128 * LDKH;
constexpr int NSTAGE = 3;
constexpr int SMEM_G = NSTAGE * 2 * TILE_H * 2;  // 61440 B

template<int EPI>
__global__ __launch_bounds__(256, 2)
void gemm_mma(const __half* __restrict__ A,     // [M,K] row-major fp16
              const __half* __restrict__ Bt,    // [N,K] row-major fp16
              const float* __restrict__ bias,   // [N]
              const float* __restrict__ resid,  // [M,N] (EPI==1)
              void* __restrict__ outv,
              int Nn, int Kk)
{
    extern __shared__ __half smh[];
    const uint32_t sb = smem_u32(smh);
    const int tid  = threadIdx.x;
    const int wid  = tid >> 5;
    const int lane = tid & 31;
    const int qr   = lane >> 2;
    const int qc   = lane & 3;
    const int bm = blockIdx.y * 128;
    const int bn = blockIdx.x * 128;
    const int warp_m = (wid & 1) * 64;
    const int warp_n = (wid >> 1) * 32;
    const int KT = Kk >> 5;

    const int lane15 = lane & 15;
    const int lanehi = lane >> 4;
    const int bl8    = lane & 7;
    const int blg    = lane >> 3;

    auto issue = [&](int buf, int k0) {
        const uint32_t ao = sb + (uint32_t)(2 * buf * TILE_H) * 2;
        const uint32_t bo = ao + TILE_H * 2;
        #pragma unroll
        for (int i = 0; i < 2; i++) {
            int idx = i * 256 + tid;
            int r = idx >> 2, c = idx & 3;
            cp_async16(ao + r * 80 + c * 16, &A[(size_t)(bm + r) * Kk + k0 + c * 8]);
        }
        #pragma unroll
        for (int i = 0; i < 2; i++) {
            int idx = i * 256 + tid;
            int r = idx >> 2, c = idx & 3;
            cp_async16(bo + r * 80 + c * 16, &Bt[(size_t)(bn + r) * Kk + k0 + c * 8]);
        }
        CP_COMMIT();
    };

    float acc[4][4][4] = {};

    issue(0, 0);
    issue(1, 32);

    for (int kt = 0; kt < KT; kt++) {
        const int cur = kt % NSTAGE;
        CP_WAIT(1);
        __syncthreads();
        if (kt + 2 < KT) issue((kt + 2) % NSTAGE, (kt + 2) * 32);
        else             CP_COMMIT();

        const uint32_t ao = sb + (uint32_t)(2 * cur * TILE_H) * 2;
        const uint32_t bo = ao + TILE_H * 2;

        uint32_t bfr[4][4];
        #pragma unroll
        for (int jn = 0; jn < 4; jn++)
            ldm_x4(bfr[jn], bo + (uint32_t)(warp_n + jn * 8 + bl8) * 80 + blg * 16);

        #pragma unroll
        for (int ks = 0; ks < 2; ks++) {
            uint32_t a[4][4];
            #pragma unroll
            for (int im = 0; im < 4; im++)
                ldm_x4(a[im], ao + (uint32_t)(warp_m + im * 16 + lane15) * 80
                              + ks * 32 + lanehi * 16);
            #pragma unroll
            for (int im = 0; im < 4; im++)
                #pragma unroll
                for (int jn = 0; jn < 4; jn++)
                    mma_f16(acc[im][jn], a[im], &bfr[jn][ks * 2]);
        }
    }

    // epilogue
    #pragma unroll
    for (int im = 0; im < 4; im++) {
        const int r0 = bm + warp_m + im * 16 + qr;
        const int r1 = r0 + 8;
        #pragma unroll
        for (int jn = 0; jn < 4; jn++) {
            const int c0 = bn + warp_n + jn * 8 + qc * 2;
            const float2 bv = *(const float2*)&bias[c0];
            float2 v0, v1;
            v0.x = acc[im][jn][0] + bv.x;
            v0.y = acc[im][jn][1] + bv.y;
            v1.x = acc[im][jn][2] + bv.x;
            v1.y = acc[im][jn][3] + bv.y;
            if (EPI == 2) {
                v0.x = 0.5f * v0.x * (1.0f + erff(v0.x * 0.70710678118654752f));
                v0.y = 0.5f * v0.y * (1.0f + erff(v0.y * 0.70710678118654752f));
                v1.x = 0.5f * v1.x * (1.0f + erff(v1.x * 0.70710678118654752f));
                v1.y = 0.5f * v1.y * (1.0f + erff(v1.y * 0.70710678118654752f));
                __half* out = (__half*)outv;
                *(__half2*)&out[(size_t)r0 * Nn + c0] = __floats2half2_rn(v0.x, v0.y);
                *(__half2*)&out[(size_t)r1 * Nn + c0] = __floats2half2_rn(v1.x, v1.y);
            } else if (EPI == 1) {
                const float2 q0 = *(const float2*)&resid[(size_t)r0 * Nn + c0];
                const float2 q1 = *(const float2*)&resid[(size_t)r1 * Nn + c0];
                float* out = (float*)outv;
                v0.x += q0.x; v0.y += q0.y;
                v1.x += q1.x; v1.y += q1.y;
                *(float2*)&out[(size_t)r0 * Nn + c0] = v0;
                *(float2*)&out[(size_t)r1 * Nn + c0] = v1;
            } else {
                const int mat = c0 >> 10;
                if (mat == 0) {      // fold 1/sqrt(D) * log2(e) into Q
                    constexpr float QS = 0.125f * 1.4426950408889634f;
                    v0.x *= QS; v0.y *= QS;
                    v1.x *= QS; v1.y *= QS;
                }
                const int cc = c0 & 1023;
                const int hi = cc >> 6, dd = cc & 63;
                __half* ob = (__half*)outv + (size_t)mat * M * C;
                {
                    const int bi = r0 >> 11, t = r0 & 2047;
                    *(__half2*)&ob[(((size_t)(bi * Hh + hi)) * T + t) * Dd + dd] =
                        __floats2half2_rn(v0.x, v0.y);
                }
                {
                    const int bi = r1 >> 11, t = r1 & 2047;
                    *(__half2*)&ob[(((size_t)(bi * Hh + hi)) * T + t) * Dd + dd] =
                        __floats2half2_rn(v1.x, v1.y);
                }
            }
        }
    }
}

// ---------------- fp16 flash attention: 64-row Q, 4 warps, P-in-register ----
// S is in log2 domain (Q pre-scaled by log2e/8); softmax uses exp2f.
constexpr int LDAH = 72;                     // halfs per row (144 B)
constexpr int SK0_H = 64 * LDAH;             // after Q (64 rows)
constexpr int SV0_H = 3 * 64 * LDAH;
constexpr int SMEM_ATT = 5 * 64 * LDAH * 2;  // Q|K0|K1|V0|V1 = 46080 B

__global__ __launch_bounds__(128)
void attn_mma(const __half* __restrict__ Q,
              const __half* __restrict__ K,
              const __half* __restrict__ V,
              __half* __restrict__ Y)
{
    extern __shared__ __half smh[];
    const uint32_t sb = smem_u32(smh);
    const int tid  = threadIdx.x;
    const int wid  = tid >> 5;
    const int lane = tid & 31;
    const int qr   = lane >> 2;
    const int qc   = lane & 3;
    const int lane15 = lane & 15;
    const int lanehi = lane >> 4;
    const int bl8    = lane & 7;
    const int blg    = lane >> 3;

    const int bh = blockIdx.y;
    const int qb = (int)gridDim.x - 1 - (int)blockIdx.x;   // heavy CTAs first

    const __half* Qp = Q + (size_t)bh * T * Dd + (size_t)qb * 64 * Dd;
    const __half* Kp = K + (size_t)bh * T * Dd;
    const __half* Vp = V + (size_t)bh * T * Dd;

    #pragma unroll
    for (int i = 0; i < 4; i++) {
        int idx = i * 128 + tid;
        int r = idx >> 3, c = idx & 7;
        *(float4*)((char*)smh + r * 144 + c * 16) = *(const float4*)&Qp[r * 64 + c * 8];
    }

    auto issue_kv = [&](int buf, int kt) {
        const uint32_t kb = sb + (uint32_t)(SK0_H + buf * 64 * LDAH) * 2;
        const uint32_t vb = sb + (uint32_t)(SV0_H + buf * 64 * LDAH) * 2;
        const __half* Ks = Kp + (size_t)kt * 64 * 64;
        const __half* Vs = Vp + (size_t)kt * 64 * 64;
        #pragma unroll
        for (int i = 0; i < 4; i++) {
            int idx = i * 128 + tid;
            int r = idx >> 3, c = idx & 7;
            cp_async16(kb + r * 144 + c * 16, Ks + r * 64 + c * 8);
        }
        #pragma unroll
        for (int i = 0; i < 4; i++) {
            int idx = i * 128 + tid;
            int r = idx >> 3, c = idx & 7;
            cp_async16(vb + r * 144 + c * 16, Vs + r * 64 + c * 8);
        }
        CP_COMMIT();
    };

    issue_kv(0, 0);
    __syncthreads();   // Q visible

    uint32_t qf[4][4];
    #pragma unroll
    for (int kc = 0; kc < 4; kc++)
        ldm_x4(qf[kc], sb + (uint32_t)(wid * 16 + lane15) * 144 + kc * 32 + lanehi * 16);

    float o[8][4] = {};
    float m0 = -1e30f, m1 = -1e30f, l0 = 0.0f, l1 = 0.0f;

    for (int kt = 0; kt <= qb; kt++) {
        const int cur = kt & 1;
        if (kt < qb) issue_kv(1 - cur, kt + 1);
        if (kt < qb) { CP_WAIT(1); } else { CP_WAIT(0); }
        __syncthreads();

        const uint32_t kb = sb + (uint32_t)(SK0_H + cur * 64 * LDAH) * 2;
        const uint32_t vb = sb + (uint32_t)(SV0_H + cur * 64 * LDAH) * 2;

        // ---- S = Q K^T (16x64 per warp), log2 domain ----
        float sacc[8][4];
        #pragma unroll
        for (int jb = 0; jb < 8; jb++) {
            sacc[jb][0] = sacc[jb][1] = sacc[jb][2] = sacc[jb][3] = 0.0f;
            uint32_t r1[4], r2[4];
            ldm_x4(r1, kb + (uint32_t)(jb * 8 + bl8) * 144 + blg * 16);
            ldm_x4(r2, kb + (uint32_t)(jb * 8 + bl8) * 144 + blg * 16 + 64);
            mma_f16(sacc[jb], qf[0], &r1[0]);
            mma_f16(sacc[jb], qf[1], &r1[2]);
            mma_f16(sacc[jb], qf[2], &r2[0]);
            mma_f16(sacc[jb], qf[3], &r2[2]);
        }

        if (kt == qb) {   // causal mask on diagonal tile
            const int row0 = wid * 16 + qr;
            const int row1 = row0 + 8;
            #pragma unroll
            for (int jb = 0; jb < 8; jb++) {
                const int cb = jb * 8 + 2 * qc;
                if (cb     > row0) sacc[jb][0] = -1e30f;
                if (cb + 1 > row0) sacc[jb][1] = -1e30f;
                if (cb     > row1) sacc[jb][2] = -1e30f;
                if (cb + 1 > row1) sacc[jb][3] = -1e30f;
            }
        }

        // ---- online softmax (base-2) ----
        float r0 = -1e30f, r1 = -1e30f;
        #pragma unroll
        for (int jb = 0; jb < 8; jb++) {
            r0 = fmaxf(r0, fmaxf(sacc[jb][0], sacc[jb][1]));
            r1 = fmaxf(r1, fmaxf(sacc[jb][2], sacc[jb][3]));
        }
        r0 = fmaxf(r0, __shfl_xor_sync(0xffffffffu, r0, 1));
        r0 = fmaxf(r0, __shfl_xor_sync(0xffffffffu, r0, 2));
        r1 = fmaxf(r1, __shfl_xor_sync(0xffffffffu, r1, 1));
        r1 = fmaxf(r1, __shfl_xor_sync(0xffffffffu, r1, 2));

        const float mn0 = fmaxf(m0, r0), mn1 = fmaxf(m1, r1);
        const float cr0 = exp2f(m0 - mn0), cr1 = exp2f(m1 - mn1);
        m0 = mn0; m1 = mn1;
        l0 *= cr0; l1 *= cr1;
        #pragma unroll
        for (int db = 0; db < 8; db++) {
            o[db][0] *= cr0; o[db][1] *= cr0;
            o[db][2] *= cr1; o[db][3] *= cr1;
        }

        // P = 2^(S - m) packed directly into A-fragments (FA2 layout identity)
        uint32_t pf[4][4];
        #pragma unroll
        for (int jb = 0; jb < 8; jb++) {
            float p0 = exp2f(sacc[jb][0] - m0);
            float p1 = exp2f(sacc[jb][1] - m0);
            float p2 = exp2f(sacc[jb][2] - m1);
            float p3 = exp2f(sacc[jb][3] - m1);
            l0 += p0 + p1; l1 += p2 + p3;
            const int kc = jb >> 1;
            const int hh = (jb & 1) * 2;
            pf[kc][hh]     = packh2(p0, p1);
            pf[kc][hh + 1] = packh2(p2, p3);
        }

        // ---- O += P V ----
        #pragma unroll
        for (int dn = 0; dn < 8; dn++) {
            uint32_t v1[4], v2[4];
            ldm_x4_t(v1, vb + (uint32_t)lane * 144 + dn * 16);
            ldm_x4_t(v2, vb + (uint32_t)(32 + lane) * 144 + dn * 16);
            mma_f16(o[dn], pf[0], &v1[0]);
            mma_f16(o[dn], pf[1], &v1[2]);
            mma_f16(o[dn], pf[2], &v2[0]);
            mma_f16(o[dn], pf[3], &v2[2]);
        }
        if (kt < qb) __syncthreads();   // guard buffer refill (none after last tile)
    }

    l0 += __shfl_xor_sync(0xffffffffu, l0, 1);
    l0 += __shfl_xor_sync(0xffffffffu, l0, 2);
    l1 += __shfl_xor_sync(0xffffffffu, l1, 1);
    l1 += __shfl_xor_sync(0xffffffffu, l1, 2);
    const float inv0 = 1.0f / l0, inv1 = 1.0f / l1;

    const int bi = bh >> 4, hi = bh & 15;
    const int q0 = qb * 64 + wid * 16 + qr;
    const int q1 = q0 + 8;
    __half* y0 = Y + ((size_t)(bi * T + q0)) * C + hi * Dd;
    __half* y1 = Y + ((size_t)(bi * T + q1)) * C + hi * Dd;
    #pragma unroll
    for (int dn = 0; dn < 8; dn++) {
        const int d = dn * 8 + 2 * qc;
        *(__half2*)&y0[d] = __floats2half2_rn(o[dn][0] * inv0, o[dn][1] * inv0);
        *(__half2*)&y1[d] = __floats2half2_rn(o[dn][2] * inv1, o[dn][3] * inv1);
    }
}

// ---------------- QKV weight transpose -> fp16 [N][K] (+ bias pack) ----------
__global__ void transpose_qkv(const float* __restrict__ wq, const float* __restrict__ wk,
                              const float* __restrict__ wv,
                              __half* __restrict__ oq, __half* __restrict__ ok,
                              __half* __restrict__ ov,
                              const float* __restrict__ bq, const float* __restrict__ bk,
                              const float* __restrict__ bv, float* __restrict__ bqkv)
{
    __shared__ float tile[32][33];
    const int z = blockIdx.z;
    const float* in = (z == 0) ? wq : (z == 1) ? wk : wv;
    __half* out = (z == 0) ? oq : (z == 1) ? ok : ov;
    int x = blockIdx.x * 32 + threadIdx.x;
    int y = blockIdx.y * 32 + threadIdx.y;
    #pragma unroll
    for (int j = 0; j < 32; j += 8)
        tile[threadIdx.y + j][threadIdx.x] = in[(size_t)(y + j) * C + x];
    __syncthreads();
    int xo = blockIdx.y * 32 + threadIdx.x;
    int yo = blockIdx.x * 32 + threadIdx.y;
    #pragma unroll
    for (int j = 0; j < 32; j += 8)
        out[(size_t)(yo + j) * C + xo] = __float2half_rn(tile[threadIdx.x][threadIdx.y + j]);

    if (z == 2 && blockIdx.x == 0 && blockIdx.y == 0) {
        int t = threadIdx.y * 32 + threadIdx.x;
        for (int i = t; i < 3 * C; i += 256) {
            const float* src = (i < C) ? bq : (i < 2 * C) ? bk : bv;
            bqkv[i] = src[i & (C - 1)];
        }
    }
}

__global__ void transpose_h(const float* __restrict__ in, __half* __restrict__ out,
                            int R, int Cc)
{
    __shared__ float tile[32][33];
    int x = blockIdx.x * 32 + threadIdx.x;
    int y = blockIdx.y * 32 + threadIdx.y;
    #pragma unroll
    for (int j = 0; j < 32; j += 8)
        tile[threadIdx.y + j][threadIdx.x] = in[(size_t)(y + j) * Cc + x];
    __syncthreads();
    int xo = blockIdx.y * 32 + threadIdx.x;
    int yo = blockIdx.x * 32 + threadIdx.y;
    #pragma unroll
    for (int j = 0; j < 32; j += 8)
        out[(size_t)(yo + j) * R + xo] = __float2half_rn(tile[threadIdx.x][threadIdx.y + j]);
}

// ---------------- LayerNorm: warp-per-row, fp16 row cache (low regs) ---------
__global__ __launch_bounds__(512)
void ln_kernel(const float* __restrict__ X,
               const float* __restrict__ w,
               const float* __restrict__ b,
               __half* __restrict__ out)
{
    const int lane = threadIdx.x & 31;
    const int row  = blockIdx.x * 16 + (threadIdx.x >> 5);
    const float* xr = X + (size_t)row * C;

    __half2 xh[16];
    float s = 0.0f, sq = 0.0f;
    #pragma unroll
    for (int i = 0; i < 8; i++) {
        const float4 v = *(const float4*)&xr[(i * 32 + lane) * 4];
        s  += v.x + v.y + v.z + v.w;
        sq += v.x*v.x + v.y*v.y + v.z*v.z + v.w*v.w;
        xh[2*i]     = __floats2half2_rn(v.x, v.y);
        xh[2*i + 1] = __floats2half2_rn(v.z, v.w);
    }
    #pragma unroll
    for (int off = 16; off > 0; off >>= 1) {
        s  += __shfl_xor_sync(0xffffffffu, s,  off);
        sq += __shfl_xor_sync(0xffffffffu, sq, off);
    }
    const float mu = s * (1.0f / C);
    const float r  = rsqrtf(sq * (1.0f / C) - mu * mu + 1e-5f);

    __half* orow = out + (size_t)row * C;
    #pragma unroll
    for (int i = 0; i < 8; i++) {
        const int c = (i * 32 + lane) * 4;
        const float4 wv = *(const float4*)&w[c];
        const float4 bv = *(const float4*)&b[c];
        const float2 a0 = __half22float2(xh[2*i]);
        const float2 a1 = __half22float2(xh[2*i + 1]);
        __half2 h0 = __floats2half2_rn((a0.x - mu) * r * wv.x + bv.x,
                                       (a0.y - mu) * r * wv.y + bv.y);
        __half2 h1 = __floats2half2_rn((a1.x - mu) * r * wv.z + bv.z,
                                       (a1.y - mu) * r * wv.w + bv.w);
        *(__half2*)&orow[c]     = h0;
        *(__half2*)&orow[c + 2] = h1;
    }
}

// ---------------- launcher ----------------------------------------------------
extern "C" void kernel_launch(void* const* d_in, const int* in_sizes, int n_in,
                              void* d_out, int out_size)
{
    const float* x     = (const float*)d_in[0];
    const float* ln1_w = (const float*)d_in[1];
    const float* ln1_b = (const float*)d_in[2];
    const float* wq    = (const float*)d_in[3];
    const float* bq    = (const float*)d_in[4];
    const float* wk    = (const float*)d_in[5];
    const float* bk    = (const float*)d_in[6];
    const float* wv    = (const float*)d_in[7];
    const float* bv    = (const float*)d_in[8];
    const float* wo    = (const float*)d_in[9];
    const float* bo    = (const float*)d_in[10];
    const float* ln2_w = (const float*)d_in[11];
    const float* ln2_b = (const float*)d_in[12];
    const float* w1    = (const float*)d_in[13];
    const float* b1    = (const float*)d_in[14];
    const float* w2    = (const float*)d_in[15];
    const float* b2    = (const float*)d_in[16];

    __half *h, *qkv, *y, *hid, *wtqkv, *wto, *wt1, *wt2;
    float *x1, *bqkv;
    cudaGetSymbolAddress((void**)&h,     g_h);
    cudaGetSymbolAddress((void**)&qkv,   g_qkv);
    cudaGetSymbolAddress((void**)&y,     g_y);
    cudaGetSymbolAddress((void**)&x1,    g_x1);
    cudaGetSymbolAddress((void**)&hid,   g_hid);
    cudaGetSymbolAddress((void**)&wtqkv, g_wtqkv);
    cudaGetSymbolAddress((void**)&bqkv,  g_bqkv);
    cudaGetSymbolAddress((void**)&wto,   g_wto);
    cudaGetSymbolAddress((void**)&wt1,   g_wt1);
    cudaGetSymbolAddress((void**)&wt2,   g_wt2);

    float* out = (float*)d_out;
    __half* q = qkv;
    __half* k = qkv + (size_t)M * C;
    __half* v = qkv + (size_t)2 * M * C;

    cudaFuncSetAttribute(gemm_mma<0>, cudaFuncAttributeMaxDynamicSharedMemorySize, SMEM_G);
    cudaFuncSetAttribute(gemm_mma<1>, cudaFuncAttributeMaxDynamicSharedMemorySize, SMEM_G);
    cudaFuncSetAttribute(gemm_mma<2>, cudaFuncAttributeMaxDynamicSharedMemorySize, SMEM_G);
    cudaFuncSetAttribute(attn_mma,    cudaFuncAttributeMaxDynamicSharedMemorySize, SMEM_ATT);

    // fork low-priority side stream for weight prep
    cudaEventRecord(g_ps.e0, 0);
    cudaStreamWaitEvent(g_ps.s1, g_ps.e0, 0);

    dim3 tb(32, 8);
    // e1 gates ONLY what the QKV GEMM needs (wq/wk/wv + bias)
    transpose_qkv<<<dim3(C/32, C/32, 3), tb, 0, g_ps.s1>>>(
        wq, wk, wv, wtqkv, wtqkv + C * C, wtqkv + 2 * C * C, bq, bk, bv, bqkv);
    cudaEventRecord(g_ps.e1, g_ps.s1);
    // wo/w1/w2 finish during the QKV GEMM; gated by e2 before attention
    transpose_h<<<dim3(C/32,  C/32),  tb, 0, g_ps.s1>>>(wo, wto, C,  C);
    transpose_h<<<dim3(FF/32, C/32),  tb, 0, g_ps.s1>>>(w1, wt1, C,  FF);
    transpose_h<<<dim3(C/32,  FF/32), tb, 0, g_ps.s1>>>(w2, wt2, FF, C);
    cudaEventRecord(g_ps.e2, g_ps.s1);

    // main stream: LN1 overlaps qkv transpose
    ln_kernel<<<M / 16, 512>>>(x, ln1_w, ln1_b, h);
    cudaStreamWaitEvent(0, g_ps.e1, 0);          // need wtqkv + bqkv
    gemm_mma<0><<<dim3(3*C/128, M/128), 256, SMEM_G>>>(h, wtqkv, bqkv, nullptr, qkv, 3*C, C);
    cudaStreamWaitEvent(0, g_ps.e2, 0);          // wto/w1/w2 ready (free wait here)
    attn_mma<<<dim3(T/64, Bb*Hh), 128, SMEM_ATT>>>(q, k, v, y);
    gemm_mma<1><<<dim3(C/128,  M/128), 256, SMEM_G>>>(y, wto, bo, x, x1, C, C);
    ln_kernel<<<M / 16, 512>>>(x1, ln2_w, ln2_b, h);
    gemm_mma<2><<<dim3(FF/128, M/128), 256, SMEM_G>>>(h, wt1, b1, nullptr, hid, FF, C);
    gemm_mma<1><<<dim3(C/128,  M/128), 256, SMEM_G>>>(hid, wt2, b2, x1, out, C, FF);
}

// round 16
// speedup vs baseline: 1.6820x; 1.0147x over previous
#include <cuda_runtime.h>
#include <cuda_fp16.h>
#include <math.h>
#include <cstdint>

// Problem constants
constexpr int Bb = 2;
constexpr int T  = 2048;
constexpr int C  = 1024;
constexpr int Hh = 16;
constexpr int Dd = 64;
constexpr int M  = Bb * T;       // 4096 tokens
constexpr int FF = 4 * C;        // 4096

// ---------------- scratch (static device memory; no allocation) -------------
__device__ __half g_h  [M * C];             // LN output (fp16)
__device__ __half g_qkv[(size_t)3 * M * C]; // q|k|v head layout; q pre-scaled by log2e/8
__device__ __half g_y  [M * C];             // attn out (fp16)
__device__ float  g_x1 [M * C];             // residual stream (fp32)
__device__ __half g_hid[(size_t)M * FF];    // MLP hidden (fp16)
// transposed weights, [N][K] layout, fp16
__device__ __half g_wtqkv[(size_t)3 * C * C];
__device__ float  g_bqkv [3 * C];
__device__ __half g_wto[C * C];
__device__ __half g_wt1[(size_t)C * FF];
__device__ __half g_wt2[(size_t)C * FF];

// ---------------- side stream + events (created before harness checkpoints) --
struct PrepStreams {
    cudaStream_t s1;
    cudaEvent_t e0, e1, e2;
    PrepStreams() {
        int least = 0, greatest = 0;
        cudaDeviceGetStreamPriorityRange(&least, &greatest);
        cudaStreamCreateWithPriority(&s1, cudaStreamNonBlocking, least);  // lowest prio
        cudaEventCreateWithFlags(&e0, cudaEventDisableTiming);
        cudaEventCreateWithFlags(&e1, cudaEventDisableTiming);
        cudaEventCreateWithFlags(&e2, cudaEventDisableTiming);
    }
};
static PrepStreams g_ps;

// ---------------- helpers ----------------------------------------------------
__device__ __forceinline__ uint32_t smem_u32(const void* p) {
    uint32_t a;
    asm("{ .reg .u64 t; cvta.to.shared.u64 t, %1; cvt.u32.u64 %0, t; }"
        : "=r"(a) : "l"(p));
    return a;
}
__device__ __forceinline__ void cp_async16(uint32_t dst, const void* src) {
    asm volatile("cp.async.cg.shared.global [%0], [%1], 16;"
                 :: "r"(dst), "l"(src) : "memory");
}
#define CP_COMMIT() asm volatile("cp.async.commit_group;" ::: "memory")
#define CP_WAIT(n)  asm volatile("cp.async.wait_group %0;" :: "n"(n) : "memory")

__device__ __forceinline__ void mma_f16(float* c, const uint32_t* a, const uint32_t* b) {
    asm volatile(
        "mma.sync.aligned.m16n8k16.row.col.f32.f16.f16.f32 "
        "{%0,%1,%2,%3}, {%4,%5,%6,%7}, {%8,%9}, {%0,%1,%2,%3};"
        : "+f"(c[0]), "+f"(c[1]), "+f"(c[2]), "+f"(c[3])
        : "r"(a[0]), "r"(a[1]), "r"(a[2]), "r"(a[3]), "r"(b[0]), "r"(b[1]));
}
__device__ __forceinline__ void ldm_x4(uint32_t* r, uint32_t addr) {
    asm volatile("ldmatrix.sync.aligned.m8n8.x4.shared.b16 {%0,%1,%2,%3}, [%4];"
        : "=r"(r[0]), "=r"(r[1]), "=r"(r[2]), "=r"(r[3]) : "r"(addr));
}
__device__ __forceinline__ void ldm_x4_t(uint32_t* r, uint32_t addr) {
    asm volatile("ldmatrix.sync.aligned.m8n8.x4.trans.shared.b16 {%0,%1,%2,%3}, [%4];"
        : "=r"(r[0]), "=r"(r[1]), "=r"(r[2]), "=r"(r[3]) : "r"(addr));
}
__device__ __forceinline__ uint32_t packh2(float a, float b) {
    __half2 h = __floats2half2_rn(a, b);
    return *(uint32_t*)&h;
}

// ---------------- fp16 mma.sync GEMM, 128x128x64, 3-stage, 2 CTA/SM ---------
// EPI: 0 = fused-QKV head-scatter (+log2e/8 on Q), 1 = residual add fp32, 2 = GELU -> fp16
// K-chunk = 64 halfs (128 B/row + 16 B pad = 144 B stride; ldmatrix conflict-free,
// same addressing as the attention kernel's 72-half rows).
constexpr int LDKG = 72;                     // halfs per smem row (144 B)
constexpr int TILEG_H = 128 * LDKG;          // halfs per matrix tile
constexpr int NSTAGE = 3;
constexpr int SMEM_G = NSTAGE * 2 * TILEG_H * 2;  // 110592 B (x2 CTA/SM = 221 KB)

template<int EPI>
__global__ __launch_bounds__(256, 2)
void gemm_mma(const __half* __restrict__ A,     // [M,K] row-major fp16
              const __half* __restrict__ Bt,    // [N,K] row-major fp16
              const float* __restrict__ bias,   // [N]
              const float* __restrict__ resid,  // [M,N] (EPI==1)
              void* __restrict__ outv,
              int Nn, int Kk)
{
    extern __shared__ __half smh[];
    const uint32_t sb = smem_u32(smh);
    const int tid  = threadIdx.x;
    const int wid  = tid >> 5;
    const int lane = tid & 31;
    const int qr   = lane >> 2;
    const int qc   = lane & 3;
    const int bm = blockIdx.y * 128;
    const int bn = blockIdx.x * 128;
    const int warp_m = (wid & 1) * 64;
    const int warp_n = (wid >> 1) * 32;
    const int KT = Kk >> 6;                 // 64-wide K chunks

    const int lane15 = lane & 15;
    const int lanehi = lane >> 4;
    const int bl8    = lane & 7;
    const int blg    = lane >> 3;

    auto issue = [&](int buf, int k0) {
        const uint32_t ao = sb + (uint32_t)(2 * buf * TILEG_H) * 2;
        const uint32_t bo = ao + TILEG_H * 2;
        #pragma unroll
        for (int i = 0; i < 4; i++) {
            int idx = i * 256 + tid;        // 1024 16B-units: 128 rows x 8
            int r = idx >> 3, c = idx & 7;
            cp_async16(ao + r * 144 + c * 16, &A[(size_t)(bm + r) * Kk + k0 + c * 8]);
        }
        #pragma unroll
        for (int i = 0; i < 4; i++) {
            int idx = i * 256 + tid;
            int r = idx >> 3, c = idx & 7;
            cp_async16(bo + r * 144 + c * 16, &Bt[(size_t)(bn + r) * Kk + k0 + c * 8]);
        }
        CP_COMMIT();
    };

    float acc[4][4][4] = {};

    issue(0, 0);
    issue(1, 64);

    for (int kt = 0; kt < KT; kt++) {
        const int cur = kt % NSTAGE;
        CP_WAIT(1);
        __syncthreads();
        if (kt + 2 < KT) issue((kt + 2) % NSTAGE, (kt + 2) * 64);
        else             CP_COMMIT();

        const uint32_t ao = sb + (uint32_t)(2 * cur * TILEG_H) * 2;
        const uint32_t bo = ao + TILEG_H * 2;

        // B fragments: 4 k16 frags per jn via two x4 loads (K[0:32), K[32:64))
        uint32_t bfr[4][8];
        #pragma unroll
        for (int jn = 0; jn < 4; jn++) {
            ldm_x4(&bfr[jn][0], bo + (uint32_t)(warp_n + jn * 8 + bl8) * 144 + blg * 16);
            ldm_x4(&bfr[jn][4], bo + (uint32_t)(warp_n + jn * 8 + bl8) * 144 + blg * 16 + 64);
        }

        #pragma unroll
        for (int ks = 0; ks < 4; ks++) {
            uint32_t a[4][4];
            #pragma unroll
            for (int im = 0; im < 4; im++)
                ldm_x4(a[im], ao + (uint32_t)(warp_m + im * 16 + lane15) * 144
                              + ks * 32 + lanehi * 16);
            #pragma unroll
            for (int im = 0; im < 4; im++)
                #pragma unroll
                for (int jn = 0; jn < 4; jn++)
                    mma_f16(acc[im][jn], a[im], &bfr[jn][ks * 2]);
        }
    }

    // epilogue
    #pragma unroll
    for (int im = 0; im < 4; im++) {
        const int r0 = bm + warp_m + im * 16 + qr;
        const int r1 = r0 + 8;
        #pragma unroll
        for (int jn = 0; jn < 4; jn++) {
            const int c0 = bn + warp_n + jn * 8 + qc * 2;
            const float2 bv = *(const float2*)&bias[c0];
            float2 v0, v1;
            v0.x = acc[im][jn][0] + bv.x;
            v0.y = acc[im][jn][1] + bv.y;
            v1.x = acc[im][jn][2] + bv.x;
            v1.y = acc[im][jn][3] + bv.y;
            if (EPI == 2) {
                v0.x = 0.5f * v0.x * (1.0f + erff(v0.x * 0.70710678118654752f));
                v0.y = 0.5f * v0.y * (1.0f + erff(v0.y * 0.70710678118654752f));
                v1.x = 0.5f * v1.x * (1.0f + erff(v1.x * 0.70710678118654752f));
                v1.y = 0.5f * v1.y * (1.0f + erff(v1.y * 0.70710678118654752f));
                __half* out = (__half*)outv;
                *(__half2*)&out[(size_t)r0 * Nn + c0] = __floats2half2_rn(v0.x, v0.y);
                *(__half2*)&out[(size_t)r1 * Nn + c0] = __floats2half2_rn(v1.x, v1.y);
            } else if (EPI == 1) {
                const float2 q0 = *(const float2*)&resid[(size_t)r0 * Nn + c0];
                const float2 q1 = *(const float2*)&resid[(size_t)r1 * Nn + c0];
                float* out = (float*)outv;
                v0.x += q0.x; v0.y += q0.y;
                v1.x += q1.x; v1.y += q1.y;
                *(float2*)&out[(size_t)r0 * Nn + c0] = v0;
                *(float2*)&out[(size_t)r1 * Nn + c0] = v1;
            } else {
                const int mat = c0 >> 10;
                if (mat == 0) {      // fold 1/sqrt(D) * log2(e) into Q
                    constexpr float QS = 0.125f * 1.4426950408889634f;
                    v0.x *= QS; v0.y *= QS;
                    v1.x *= QS; v1.y *= QS;
                }
                const int cc = c0 & 1023;
                const int hi = cc >> 6, dd = cc & 63;
                __half* ob = (__half*)outv + (size_t)mat * M * C;
                {
                    const int bi = r0 >> 11, t = r0 & 2047;
                    *(__half2*)&ob[(((size_t)(bi * Hh + hi)) * T + t) * Dd + dd] =
                        __floats2half2_rn(v0.x, v0.y);
                }
                {
                    const int bi = r1 >> 11, t = r1 & 2047;
                    *(__half2*)&ob[(((size_t)(bi * Hh + hi)) * T + t) * Dd + dd] =
                        __floats2half2_rn(v1.x, v1.y);
                }
            }
        }
    }
}

// ---------------- fp16 flash attention: 64-row Q, 4 warps, P-in-register ----
// S is in log2 domain (Q pre-scaled by log2e/8); softmax uses exp2f.
constexpr int LDAH = 72;                     // halfs per row (144 B)
constexpr int SK0_H = 64 * LDAH;             // after Q (64 rows)
constexpr int SV0_H = 3 * 64 * LDAH;
constexpr int SMEM_ATT = 5 * 64 * LDAH * 2;  // Q|K0|K1|V0|V1 = 46080 B

__global__ __launch_bounds__(128)
void attn_mma(const __half* __restrict__ Q,
              const __half* __restrict__ K,
              const __half* __restrict__ V,
              __half* __restrict__ Y)
{
    extern __shared__ __half smh[];
    const uint32_t sb = smem_u32(smh);
    const int tid  = threadIdx.x;
    const int wid  = tid >> 5;
    const int lane = tid & 31;
    const int qr   = lane >> 2;
    const int qc   = lane & 3;
    const int lane15 = lane & 15;
    const int lanehi = lane >> 4;
    const int bl8    = lane & 7;
    const int blg    = lane >> 3;

    const int bh = blockIdx.y;
    const int qb = (int)gridDim.x - 1 - (int)blockIdx.x;   // heavy CTAs first

    const __half* Qp = Q + (size_t)bh * T * Dd + (size_t)qb * 64 * Dd;
    const __half* Kp = K + (size_t)bh * T * Dd;
    const __half* Vp = V + (size_t)bh * T * Dd;

    #pragma unroll
    for (int i = 0; i < 4; i++) {
        int idx = i * 128 + tid;
        int r = idx >> 3, c = idx & 7;
        *(float4*)((char*)smh + r * 144 + c * 16) = *(const float4*)&Qp[r * 64 + c * 8];
    }

    auto issue_kv = [&](int buf, int kt) {
        const uint32_t kb = sb + (uint32_t)(SK0_H + buf * 64 * LDAH) * 2;
        const uint32_t vb = sb + (uint32_t)(SV0_H + buf * 64 * LDAH) * 2;
        const __half* Ks = Kp + (size_t)kt * 64 * 64;
        const __half* Vs = Vp + (size_t)kt * 64 * 64;
        #pragma unroll
        for (int i = 0; i < 4; i++) {
            int idx = i * 128 + tid;
            int r = idx >> 3, c = idx & 7;
            cp_async16(kb + r * 144 + c * 16, Ks + r * 64 + c * 8);
        }
        #pragma unroll
        for (int i = 0; i < 4; i++) {
            int idx = i * 128 + tid;
            int r = idx >> 3, c = idx & 7;
            cp_async16(vb + r * 144 + c * 16, Vs + r * 64 + c * 8);
        }
        CP_COMMIT();
    };

    issue_kv(0, 0);
    __syncthreads();   // Q visible

    uint32_t qf[4][4];
    #pragma unroll
    for (int kc = 0; kc < 4; kc++)
        ldm_x4(qf[kc], sb + (uint32_t)(wid * 16 + lane15) * 144 + kc * 32 + lanehi * 16);

    float o[8][4] = {};
    float m0 = -1e30f, m1 = -1e30f, l0 = 0.0f, l1 = 0.0f;

    for (int kt = 0; kt <= qb; kt++) {
        const int cur = kt & 1;
        if (kt < qb) issue_kv(1 - cur, kt + 1);
        if (kt < qb) { CP_WAIT(1); } else { CP_WAIT(0); }
        __syncthreads();

        const uint32_t kb = sb + (uint32_t)(SK0_H + cur * 64 * LDAH) * 2;
        const uint32_t vb = sb + (uint32_t)(SV0_H + cur * 64 * LDAH) * 2;

        // ---- S = Q K^T (16x64 per warp), log2 domain ----
        float sacc[8][4];
        #pragma unroll
        for (int jb = 0; jb < 8; jb++) {
            sacc[jb][0] = sacc[jb][1] = sacc[jb][2] = sacc[jb][3] = 0.0f;
            uint32_t r1[4], r2[4];
            ldm_x4(r1, kb + (uint32_t)(jb * 8 + bl8) * 144 + blg * 16);
            ldm_x4(r2, kb + (uint32_t)(jb * 8 + bl8) * 144 + blg * 16 + 64);
            mma_f16(sacc[jb], qf[0], &r1[0]);
            mma_f16(sacc[jb], qf[1], &r1[2]);
            mma_f16(sacc[jb], qf[2], &r2[0]);
            mma_f16(sacc[jb], qf[3], &r2[2]);
        }

        if (kt == qb) {   // causal mask on diagonal tile
            const int row0 = wid * 16 + qr;
            const int row1 = row0 + 8;
            #pragma unroll
            for (int jb = 0; jb < 8; jb++) {
                const int cb = jb * 8 + 2 * qc;
                if (cb     > row0) sacc[jb][0] = -1e30f;
                if (cb + 1 > row0) sacc[jb][1] = -1e30f;
                if (cb     > row1) sacc[jb][2] = -1e30f;
                if (cb + 1 > row1) sacc[jb][3] = -1e30f;
            }
        }

        // ---- online softmax (base-2) ----
        float r0 = -1e30f, r1 = -1e30f;
        #pragma unroll
        for (int jb = 0; jb < 8; jb++) {
            r0 = fmaxf(r0, fmaxf(sacc[jb][0], sacc[jb][1]));
            r1 = fmaxf(r1, fmaxf(sacc[jb][2], sacc[jb][3]));
        }
        r0 = fmaxf(r0, __shfl_xor_sync(0xffffffffu, r0, 1));
        r0 = fmaxf(r0, __shfl_xor_sync(0xffffffffu, r0, 2));
        r1 = fmaxf(r1, __shfl_xor_sync(0xffffffffu, r1, 1));
        r1 = fmaxf(r1, __shfl_xor_sync(0xffffffffu, r1, 2));

        const float mn0 = fmaxf(m0, r0), mn1 = fmaxf(m1, r1);
        const float cr0 = exp2f(m0 - mn0), cr1 = exp2f(m1 - mn1);
        m0 = mn0; m1 = mn1;
        l0 *= cr0; l1 *= cr1;
        #pragma unroll
        for (int db = 0; db < 8; db++) {
            o[db][0] *= cr0; o[db][1] *= cr0;
            o[db][2] *= cr1; o[db][3] *= cr1;
        }

        // P = 2^(S - m) packed directly into A-fragments (FA2 layout identity)
        uint32_t pf[4][4];
        #pragma unroll
        for (int jb = 0; jb < 8; jb++) {
            float p0 = exp2f(sacc[jb][0] - m0);
            float p1 = exp2f(sacc[jb][1] - m0);
            float p2 = exp2f(sacc[jb][2] - m1);
            float p3 = exp2f(sacc[jb][3] - m1);
            l0 += p0 + p1; l1 += p2 + p3;
            const int kc = jb >> 1;
            const int hh = (jb & 1) * 2;
            pf[kc][hh]     = packh2(p0, p1);
            pf[kc][hh + 1] = packh2(p2, p3);
        }

        // ---- O += P V ----
        #pragma unroll
        for (int dn = 0; dn < 8; dn++) {
            uint32_t v1[4], v2[4];
            ldm_x4_t(v1, vb + (uint32_t)lane * 144 + dn * 16);
            ldm_x4_t(v2, vb + (uint32_t)(32 + lane) * 144 + dn * 16);
            mma_f16(o[dn], pf[0], &v1[0]);
            mma_f16(o[dn], pf[1], &v1[2]);
            mma_f16(o[dn], pf[2], &v2[0]);
            mma_f16(o[dn], pf[3], &v2[2]);
        }
        if (kt < qb) __syncthreads();   // guard buffer refill (none after last tile)
    }

    l0 += __shfl_xor_sync(0xffffffffu, l0, 1);
    l0 += __shfl_xor_sync(0xffffffffu, l0, 2);
    l1 += __shfl_xor_sync(0xffffffffu, l1, 1);
    l1 += __shfl_xor_sync(0xffffffffu, l1, 2);
    const float inv0 = 1.0f / l0, inv1 = 1.0f / l1;

    const int bi = bh >> 4, hi = bh & 15;
    const int q0 = qb * 64 + wid * 16 + qr;
    const int q1 = q0 + 8;
    __half* y0 = Y + ((size_t)(bi * T + q0)) * C + hi * Dd;
    __half* y1 = Y + ((size_t)(bi * T + q1)) * C + hi * Dd;
    #pragma unroll
    for (int dn = 0; dn < 8; dn++) {
        const int d = dn * 8 + 2 * qc;
        *(__half2*)&y0[d] = __floats2half2_rn(o[dn][0] * inv0, o[dn][1] * inv0);
        *(__half2*)&y1[d] = __floats2half2_rn(o[dn][2] * inv1, o[dn][3] * inv1);
    }
}

// ---------------- QKV weight transpose -> fp16 [N][K] (+ bias pack) ----------
__global__ void transpose_qkv(const float* __restrict__ wq, const float* __restrict__ wk,
                              const float* __restrict__ wv,
                              __half* __restrict__ oq, __half* __restrict__ ok,
                              __half* __restrict__ ov,
                              const float* __restrict__ bq, const float* __restrict__ bk,
                              const float* __restrict__ bv, float* __restrict__ bqkv)
{
    __shared__ float tile[32][33];
    const int z = blockIdx.z;
    const float* in = (z == 0) ? wq : (z == 1) ? wk : wv;
    __half* out = (z == 0) ? oq : (z == 1) ? ok : ov;
    int x = blockIdx.x * 32 + threadIdx.x;
    int y = blockIdx.y * 32 + threadIdx.y;
    #pragma unroll
    for (int j = 0; j < 32; j += 8)
        tile[threadIdx.y + j][threadIdx.x] = in[(size_t)(y + j) * C + x];
    __syncthreads();
    int xo = blockIdx.y * 32 + threadIdx.x;
    int yo = blockIdx.x * 32 + threadIdx.y;
    #pragma unroll
    for (int j = 0; j < 32; j += 8)
        out[(size_t)(yo + j) * C + xo] = __float2half_rn(tile[threadIdx.x][threadIdx.y + j]);

    if (z == 2 && blockIdx.x == 0 && blockIdx.y == 0) {
        int t = threadIdx.y * 32 + threadIdx.x;
        for (int i = t; i < 3 * C; i += 256) {
            const float* src = (i < C) ? bq : (i < 2 * C) ? bk : bv;
            bqkv[i] = src[i & (C - 1)];
        }
    }
}

__global__ void transpose_h(const float* __restrict__ in, __half* __restrict__ out,
                            int R, int Cc)
{
    __shared__ float tile[32][33];
    int x = blockIdx.x * 32 + threadIdx.x;
    int y = blockIdx.y * 32 + threadIdx.y;
    #pragma unroll
    for (int j = 0; j < 32; j += 8)
        tile[threadIdx.y + j][threadIdx.x] = in[(size_t)(y + j) * Cc + x];
    __syncthreads();
    int xo = blockIdx.y * 32 + threadIdx.x;
    int yo = blockIdx.x * 32 + threadIdx.y;
    #pragma unroll
    for (int j = 0; j < 32; j += 8)
        out[(size_t)(yo + j) * R + xo] = __float2half_rn(tile[threadIdx.x][threadIdx.y + j]);
}

// ---------------- LayerNorm: warp-per-row, fp16 row cache (low regs) ---------
__global__ __launch_bounds__(512)
void ln_kernel(const float* __restrict__ X,
               const float* __restrict__ w,
               const float* __restrict__ b,
               __half* __restrict__ out)
{
    const int lane = threadIdx.x & 31;
    const int row  = blockIdx.x * 16 + (threadIdx.x >> 5);
    const float* xr = X + (size_t)row * C;

    __half2 xh[16];
    float s = 0.0f, sq = 0.0f;
    #pragma unroll
    for (int i = 0; i < 8; i++) {
        const float4 v = *(const float4*)&xr[(i * 32 + lane) * 4];
        s  += v.x + v.y + v.z + v.w;
        sq += v.x*v.x + v.y*v.y + v.z*v.z + v.w*v.w;
        xh[2*i]     = __floats2half2_rn(v.x, v.y);
        xh[2*i + 1] = __floats2half2_rn(v.z, v.w);
    }
    #pragma unroll
    for (int off = 16; off > 0; off >>= 1) {
        s  += __shfl_xor_sync(0xffffffffu, s,  off);
        sq += __shfl_xor_sync(0xffffffffu, sq, off);
    }
    const float mu = s * (1.0f / C);
    const float r  = rsqrtf(sq * (1.0f / C) - mu * mu + 1e-5f);

    __half* orow = out + (size_t)row * C;
    #pragma unroll
    for (int i = 0; i < 8; i++) {
        const int c = (i * 32 + lane) * 4;
        const float4 wv = *(const float4*)&w[c];
        const float4 bv = *(const float4*)&b[c];
        const float2 a0 = __half22float2(xh[2*i]);
        const float2 a1 = __half22float2(xh[2*i + 1]);
        __half2 h0 = __floats2half2_rn((a0.x - mu) * r * wv.x + bv.x,
                                       (a0.y - mu) * r * wv.y + bv.y);
        __half2 h1 = __floats2half2_rn((a1.x - mu) * r * wv.z + bv.z,
                                       (a1.y - mu) * r * wv.w + bv.w);
        *(__half2*)&orow[c]     = h0;
        *(__half2*)&orow[c + 2] = h1;
    }
}

// ---------------- launcher ----------------------------------------------------
extern "C" void kernel_launch(void* const* d_in, const int* in_sizes, int n_in,
                              void* d_out, int out_size)
{
    const float* x     = (const float*)d_in[0];
    const float* ln1_w = (const float*)d_in[1];
    const float* ln1_b = (const float*)d_in[2];
    const float* wq    = (const float*)d_in[3];
    const float* bq    = (const float*)d_in[4];
    const float* wk    = (const float*)d_in[5];
    const float* bk    = (const float*)d_in[6];
    const float* wv    = (const float*)d_in[7];
    const float* bv    = (const float*)d_in[8];
    const float* wo    = (const float*)d_in[9];
    const float* bo    = (const float*)d_in[10];
    const float* ln2_w = (const float*)d_in[11];
    const float* ln2_b = (const float*)d_in[12];
    const float* w1    = (const float*)d_in[13];
    const float* b1    = (const float*)d_in[14];
    const float* w2    = (const float*)d_in[15];
    const float* b2    = (const float*)d_in[16];

    __half *h, *qkv, *y, *hid, *wtqkv, *wto, *wt1, *wt2;
    float *x1, *bqkv;
    cudaGetSymbolAddress((void**)&h,     g_h);
    cudaGetSymbolAddress((void**)&qkv,   g_qkv);
    cudaGetSymbolAddress((void**)&y,     g_y);
    cudaGetSymbolAddress((void**)&x1,    g_x1);
    cudaGetSymbolAddress((void**)&hid,   g_hid);
    cudaGetSymbolAddress((void**)&wtqkv, g_wtqkv);
    cudaGetSymbolAddress((void**)&bqkv,  g_bqkv);
    cudaGetSymbolAddress((void**)&wto,   g_wto);
    cudaGetSymbolAddress((void**)&wt1,   g_wt1);
    cudaGetSymbolAddress((void**)&wt2,   g_wt2);

    float* out = (float*)d_out;
    __half* q = qkv;
    __half* k = qkv + (size_t)M * C;
    __half* v = qkv + (size_t)2 * M * C;

    cudaFuncSetAttribute(gemm_mma<0>, cudaFuncAttributeMaxDynamicSharedMemorySize, SMEM_G);
    cudaFuncSetAttribute(gemm_mma<1>, cudaFuncAttributeMaxDynamicSharedMemorySize, SMEM_G);
    cudaFuncSetAttribute(gemm_mma<2>, cudaFuncAttributeMaxDynamicSharedMemorySize, SMEM_G);
    cudaFuncSetAttribute(attn_mma,    cudaFuncAttributeMaxDynamicSharedMemorySize, SMEM_ATT);

    // fork low-priority side stream for weight prep
    cudaEventRecord(g_ps.e0, 0);
    cudaStreamWaitEvent(g_ps.s1, g_ps.e0, 0);

    dim3 tb(32, 8);
    // e1 gates ONLY what the QKV GEMM needs (wq/wk/wv + bias)
    transpose_qkv<<<dim3(C/32, C/32, 3), tb, 0, g_ps.s1>>>(
        wq, wk, wv, wtqkv, wtqkv + C * C, wtqkv + 2 * C * C, bq, bk, bv, bqkv);
    cudaEventRecord(g_ps.e1, g_ps.s1);
    // wo/w1/w2 finish during the QKV GEMM; gated by e2 before attention
    transpose_h<<<dim3(C/32,  C/32),  tb, 0, g_ps.s1>>>(wo, wto, C,  C);
    transpose_h<<<dim3(FF/32, C/32),  tb, 0, g_ps.s1>>>(w1, wt1, C,  FF);
    transpose_h<<<dim3(C/32,  FF/32), tb, 0, g_ps.s1>>>(w2, wt2, FF, C);
    cudaEventRecord(g_ps.e2, g_ps.s1);

    // main stream: LN1 overlaps qkv transpose
    ln_kernel<<<M / 16, 512>>>(x, ln1_w, ln1_b, h);
    cudaStreamWaitEvent(0, g_ps.e1, 0);          // need wtqkv + bqkv
    gemm_mma<0><<<dim3(3*C/128, M/128), 256, SMEM_G>>>(h, wtqkv, bqkv, nullptr, qkv, 3*C, C);
    cudaStreamWaitEvent(0, g_ps.e2, 0);          // wto/w1/w2 ready (free wait here)
    attn_mma<<<dim3(T/64, Bb*Hh), 128, SMEM_ATT>>>(q, k, v, y);
    gemm_mma<1><<<dim3(C/128,  M/128), 256, SMEM_G>>>(y, wto, bo, x, x1, C, C);
    ln_kernel<<<M / 16, 512>>>(x1, ln2_w, ln2_b, h);
    gemm_mma<2><<<dim3(FF/128, M/128), 256, SMEM_G>>>(h, wt1, b1, nullptr, hid, FF, C);
    gemm_mma<1><<<dim3(C/128,  M/128), 256, SMEM_G>>>(hid, wt2, b2, x1, out, C, FF);
}

// round 17
// speedup vs baseline: 1.6935x; 1.0069x over previous
#include <cuda_runtime.h>
#include <cuda_fp16.h>
#include <math.h>
#include <cstdint>

// Problem constants
constexpr int Bb = 2;
constexpr int T  = 2048;
constexpr int C  = 1024;
constexpr int Hh = 16;
constexpr int Dd = 64;
constexpr int M  = Bb * T;       // 4096 tokens
constexpr int FF = 4 * C;        // 4096

// ---------------- scratch (static device memory; no allocation) -------------
__device__ __half g_h  [M * C];             // LN output (fp16)
__device__ __half g_qkv[(size_t)3 * M * C]; // q|k|v head layout; q pre-scaled by log2e/8
__device__ __half g_y  [M * C];             // attn out (fp16)
__device__ float  g_x1 [M * C];             // residual stream (fp32)
__device__ __half g_hid[(size_t)M * FF];    // MLP hidden (fp16)
// transposed weights, [N][K] layout, fp16
__device__ __half g_wtqkv[(size_t)3 * C * C];
__device__ float  g_bqkv [3 * C];
__device__ __half g_wto[C * C];
__device__ __half g_wt1[(size_t)C * FF];
__device__ __half g_wt2[(size_t)C * FF];

// ---------------- side stream + events (created before harness checkpoints) --
struct PrepStreams {
    cudaStream_t s1;
    cudaEvent_t e0, e1, e2;
    PrepStreams() {
        int least = 0, greatest = 0;
        cudaDeviceGetStreamPriorityRange(&least, &greatest);
        cudaStreamCreateWithPriority(&s1, cudaStreamNonBlocking, least);  // lowest prio
        cudaEventCreateWithFlags(&e0, cudaEventDisableTiming);
        cudaEventCreateWithFlags(&e1, cudaEventDisableTiming);
        cudaEventCreateWithFlags(&e2, cudaEventDisableTiming);
    }
};
static PrepStreams g_ps;

// ---------------- helpers ----------------------------------------------------
__device__ __forceinline__ uint32_t smem_u32(const void* p) {
    uint32_t a;
    asm("{ .reg .u64 t; cvta.to.shared.u64 t, %1; cvt.u32.u64 %0, t; }"
        : "=r"(a) : "l"(p));
    return a;
}
__device__ __forceinline__ void cp_async16(uint32_t dst, const void* src) {
    asm volatile("cp.async.cg.shared.global [%0], [%1], 16;"
                 :: "r"(dst), "l"(src) : "memory");
}
#define CP_COMMIT() asm volatile("cp.async.commit_group;" ::: "memory")
#define CP_WAIT(n)  asm volatile("cp.async.wait_group %0;" :: "n"(n) : "memory")

__device__ __forceinline__ void mma_f16(float* c, const uint32_t* a, const uint32_t* b) {
    asm volatile(
        "mma.sync.aligned.m16n8k16.row.col.f32.f16.f16.f32 "
        "{%0,%1,%2,%3}, {%4,%5,%6,%7}, {%8,%9}, {%0,%1,%2,%3};"
        : "+f"(c[0]), "+f"(c[1]), "+f"(c[2]), "+f"(c[3])
        : "r"(a[0]), "r"(a[1]), "r"(a[2]), "r"(a[3]), "r"(b[0]), "r"(b[1]));
}
__device__ __forceinline__ void ldm_x4(uint32_t* r, uint32_t addr) {
    asm volatile("ldmatrix.sync.aligned.m8n8.x4.shared.b16 {%0,%1,%2,%3}, [%4];"
        : "=r"(r[0]), "=r"(r[1]), "=r"(r[2]), "=r"(r[3]) : "r"(addr));
}
__device__ __forceinline__ void ldm_x4_t(uint32_t* r, uint32_t addr) {
    asm volatile("ldmatrix.sync.aligned.m8n8.x4.trans.shared.b16 {%0,%1,%2,%3}, [%4];"
        : "=r"(r[0]), "=r"(r[1]), "=r"(r[2]), "=r"(r[3]) : "r"(addr));
}
__device__ __forceinline__ uint32_t packh2(float a, float b) {
    __half2 h = __floats2half2_rn(a, b);
    return *(uint32_t*)&h;
}
// exact-GELU via A&S 7.1.26 erf approximation (|abs err| <= 1.5e-7)
__device__ __forceinline__ float fast_gelu(float x) {
    const float ax = fabsf(x) * 0.70710678118654752f;   // |x|/sqrt(2)
    const float t  = __fdividef(1.0f, 1.0f + 0.3275911f * ax);
    float poly = 1.061405429f;
    poly = poly * t - 1.453152027f;
    poly = poly * t + 1.421413741f;
    poly = poly * t - 0.284496736f;
    poly = poly * t + 0.254829592f;
    const float erfv = copysignf(1.0f - poly * t * __expf(-ax * ax), x);
    return 0.5f * x * (1.0f + erfv);
}

// ---------------- fp16 mma.sync GEMM, 128x128x64, 3-stage, 2 CTA/SM ---------
// EPI: 0 = fused-QKV head-scatter (+log2e/8 on Q), 1 = residual add fp32, 2 = GELU -> fp16
constexpr int LDKG = 72;                     // halfs per smem row (144 B)
constexpr int TILEG_H = 128 * LDKG;          // halfs per matrix tile
constexpr int NSTAGE = 3;
constexpr int SMEM_G = NSTAGE * 2 * TILEG_H * 2;  // 110592 B (x2 CTA/SM = 221 KB)

template<int EPI>
__global__ __launch_bounds__(256, 2)
void gemm_mma(const __half* __restrict__ A,     // [M,K] row-major fp16
              const __half* __restrict__ Bt,    // [N,K] row-major fp16
              const float* __restrict__ bias,   // [N]
              const float* __restrict__ resid,  // [M,N] (EPI==1)
              void* __restrict__ outv,
              int Nn, int Kk)
{
    extern __shared__ __half smh[];
    const uint32_t sb = smem_u32(smh);
    const int tid  = threadIdx.x;
    const int wid  = tid >> 5;
    const int lane = tid & 31;
    const int qr   = lane >> 2;
    const int qc   = lane & 3;
    const int bm = blockIdx.y * 128;
    const int bn = blockIdx.x * 128;
    const int warp_m = (wid & 1) * 64;
    const int warp_n = (wid >> 1) * 32;
    const int KT = Kk >> 6;                 // 64-wide K chunks

    const int lane15 = lane & 15;
    const int lanehi = lane >> 4;
    const int bl8    = lane & 7;
    const int blg    = lane >> 3;

    auto issue = [&](int buf, int k0) {
        const uint32_t ao = sb + (uint32_t)(2 * buf * TILEG_H) * 2;
        const uint32_t bo = ao + TILEG_H * 2;
        #pragma unroll
        for (int i = 0; i < 4; i++) {
            int idx = i * 256 + tid;        // 1024 16B-units: 128 rows x 8
            int r = idx >> 3, c = idx & 7;
            cp_async16(ao + r * 144 + c * 16, &A[(size_t)(bm + r) * Kk + k0 + c * 8]);
        }
        #pragma unroll
        for (int i = 0; i < 4; i++) {
            int idx = i * 256 + tid;
            int r = idx >> 3, c = idx & 7;
            cp_async16(bo + r * 144 + c * 16, &Bt[(size_t)(bn + r) * Kk + k0 + c * 8]);
        }
        CP_COMMIT();
    };

    float acc[4][4][4] = {};

    issue(0, 0);
    issue(1, 64);

    for (int kt = 0; kt < KT; kt++) {
        const int cur = kt % NSTAGE;
        CP_WAIT(1);
        __syncthreads();
        if (kt + 2 < KT) issue((kt + 2) % NSTAGE, (kt + 2) * 64);
        else             CP_COMMIT();

        const uint32_t ao = sb + (uint32_t)(2 * cur * TILEG_H) * 2;
        const uint32_t bo = ao + TILEG_H * 2;

        // B fragments: 4 k16 frags per jn via two x4 loads (K[0:32), K[32:64))
        uint32_t bfr[4][8];
        #pragma unroll
        for (int jn = 0; jn < 4; jn++) {
            ldm_x4(&bfr[jn][0], bo + (uint32_t)(warp_n + jn * 8 + bl8) * 144 + blg * 16);
            ldm_x4(&bfr[jn][4], bo + (uint32_t)(warp_n + jn * 8 + bl8) * 144 + blg * 16 + 64);
        }

        #pragma unroll
        for (int ks = 0; ks < 4; ks++) {
            uint32_t a[4][4];
            #pragma unroll
            for (int im = 0; im < 4; im++)
                ldm_x4(a[im], ao + (uint32_t)(warp_m + im * 16 + lane15) * 144
                              + ks * 32 + lanehi * 16);
            #pragma unroll
            for (int im = 0; im < 4; im++)
                #pragma unroll
                for (int jn = 0; jn < 4; jn++)
                    mma_f16(acc[im][jn], a[im], &bfr[jn][ks * 2]);
        }
    }

    // epilogue
    #pragma unroll
    for (int im = 0; im < 4; im++) {
        const int r0 = bm + warp_m + im * 16 + qr;
        const int r1 = r0 + 8;
        #pragma unroll
        for (int jn = 0; jn < 4; jn++) {
            const int c0 = bn + warp_n + jn * 8 + qc * 2;
            const float2 bv = *(const float2*)&bias[c0];
            float2 v0, v1;
            v0.x = acc[im][jn][0] + bv.x;
            v0.y = acc[im][jn][1] + bv.y;
            v1.x = acc[im][jn][2] + bv.x;
            v1.y = acc[im][jn][3] + bv.y;
            if (EPI == 2) {
                v0.x = fast_gelu(v0.x);
                v0.y = fast_gelu(v0.y);
                v1.x = fast_gelu(v1.x);
                v1.y = fast_gelu(v1.y);
                __half* out = (__half*)outv;
                *(__half2*)&out[(size_t)r0 * Nn + c0] = __floats2half2_rn(v0.x, v0.y);
                *(__half2*)&out[(size_t)r1 * Nn + c0] = __floats2half2_rn(v1.x, v1.y);
            } else if (EPI == 1) {
                const float2 q0 = *(const float2*)&resid[(size_t)r0 * Nn + c0];
                const float2 q1 = *(const float2*)&resid[(size_t)r1 * Nn + c0];
                float* out = (float*)outv;
                v0.x += q0.x; v0.y += q0.y;
                v1.x += q1.x; v1.y += q1.y;
                *(float2*)&out[(size_t)r0 * Nn + c0] = v0;
                *(float2*)&out[(size_t)r1 * Nn + c0] = v1;
            } else {
                const int mat = c0 >> 10;
                if (mat == 0) {      // fold 1/sqrt(D) * log2(e) into Q
                    constexpr float QS = 0.125f * 1.4426950408889634f;
                    v0.x *= QS; v0.y *= QS;
                    v1.x *= QS; v1.y *= QS;
                }
                const int cc = c0 & 1023;
                const int hi = cc >> 6, dd = cc & 63;
                __half* ob = (__half*)outv + (size_t)mat * M * C;
                {
                    const int bi = r0 >> 11, t = r0 & 2047;
                    *(__half2*)&ob[(((size_t)(bi * Hh + hi)) * T + t) * Dd + dd] =
                        __floats2half2_rn(v0.x, v0.y);
                }
                {
                    const int bi = r1 >> 11, t = r1 & 2047;
                    *(__half2*)&ob[(((size_t)(bi * Hh + hi)) * T + t) * Dd + dd] =
                        __floats2half2_rn(v1.x, v1.y);
                }
            }
        }
    }
}

// ---------------- fp16 flash attention: 64-row Q, 4 warps, P-in-register ----
// S is in log2 domain (Q pre-scaled by log2e/8); softmax uses exp2f.
constexpr int LDAH = 72;                     // halfs per row (144 B)
constexpr int SK0_H = 64 * LDAH;             // after Q (64 rows)
constexpr int SV0_H = 3 * 64 * LDAH;
constexpr int SMEM_ATT = 5 * 64 * LDAH * 2;  // Q|K0|K1|V0|V1 = 46080 B

__global__ __launch_bounds__(128)
void attn_mma(const __half* __restrict__ Q,
              const __half* __restrict__ K,
              const __half* __restrict__ V,
              __half* __restrict__ Y)
{
    extern __shared__ __half smh[];
    const uint32_t sb = smem_u32(smh);
    const int tid  = threadIdx.x;
    const int wid  = tid >> 5;
    const int lane = tid & 31;
    const int qr   = lane >> 2;
    const int qc   = lane & 3;
    const int lane15 = lane & 15;
    const int lanehi = lane >> 4;
    const int bl8    = lane & 7;
    const int blg    = lane >> 3;

    const int bh = blockIdx.y;
    const int qb = (int)gridDim.x - 1 - (int)blockIdx.x;   // heavy CTAs first

    const __half* Qp = Q + (size_t)bh * T * Dd + (size_t)qb * 64 * Dd;
    const __half* Kp = K + (size_t)bh * T * Dd;
    const __half* Vp = V + (size_t)bh * T * Dd;

    #pragma unroll
    for (int i = 0; i < 4; i++) {
        int idx = i * 128 + tid;
        int r = idx >> 3, c = idx & 7;
        *(float4*)((char*)smh + r * 144 + c * 16) = *(const float4*)&Qp[r * 64 + c * 8];
    }

    auto issue_kv = [&](int buf, int kt) {
        const uint32_t kb = sb + (uint32_t)(SK0_H + buf * 64 * LDAH) * 2;
        const uint32_t vb = sb + (uint32_t)(SV0_H + buf * 64 * LDAH) * 2;
        const __half* Ks = Kp + (size_t)kt * 64 * 64;
        const __half* Vs = Vp + (size_t)kt * 64 * 64;
        #pragma unroll
        for (int i = 0; i < 4; i++) {
            int idx = i * 128 + tid;
            int r = idx >> 3, c = idx & 7;
            cp_async16(kb + r * 144 + c * 16, Ks + r * 64 + c * 8);
        }
        #pragma unroll
        for (int i = 0; i < 4; i++) {
            int idx = i * 128 + tid;
            int r = idx >> 3, c = idx & 7;
            cp_async16(vb + r * 144 + c * 16, Vs + r * 64 + c * 8);
        }
        CP_COMMIT();
    };

    issue_kv(0, 0);
    __syncthreads();   // Q visible

    uint32_t qf[4][4];
    #pragma unroll
    for (int kc = 0; kc < 4; kc++)
        ldm_x4(qf[kc], sb + (uint32_t)(wid * 16 + lane15) * 144 + kc * 32 + lanehi * 16);

    float o[8][4] = {};
    float m0 = -1e30f, m1 = -1e30f, l0 = 0.0f, l1 = 0.0f;

    for (int kt = 0; kt <= qb; kt++) {
        const int cur = kt & 1;
        if (kt < qb) issue_kv(1 - cur, kt + 1);
        if (kt < qb) { CP_WAIT(1); } else { CP_WAIT(0); }
        __syncthreads();

        const uint32_t kb = sb + (uint32_t)(SK0_H + cur * 64 * LDAH) * 2;
        const uint32_t vb = sb + (uint32_t)(SV0_H + cur * 64 * LDAH) * 2;

        // ---- S = Q K^T (16x64 per warp), log2 domain ----
        float sacc[8][4];
        #pragma unroll
        for (int jb = 0; jb < 8; jb++) {
            sacc[jb][0] = sacc[jb][1] = sacc[jb][2] = sacc[jb][3] = 0.0f;
            uint32_t r1[4], r2[4];
            ldm_x4(r1, kb + (uint32_t)(jb * 8 + bl8) * 144 + blg * 16);
            ldm_x4(r2, kb + (uint32_t)(jb * 8 + bl8) * 144 + blg * 16 + 64);
            mma_f16(sacc[jb], qf[0], &r1[0]);
            mma_f16(sacc[jb], qf[1], &r1[2]);
            mma_f16(sacc[jb], qf[2], &r2[0]);
            mma_f16(sacc[jb], qf[3], &r2[2]);
        }

        if (kt == qb) {   // causal mask on diagonal tile
            const int row0 = wid * 16 + qr;
            const int row1 = row0 + 8;
            #pragma unroll
            for (int jb = 0; jb < 8; jb++) {
                const int cb = jb * 8 + 2 * qc;
                if (cb     > row0) sacc[jb][0] = -1e30f;
                if (cb + 1 > row0) sacc[jb][1] = -1e30f;
                if (cb     > row1) sacc[jb][2] = -1e30f;
                if (cb + 1 > row1) sacc[jb][3] = -1e30f;
            }
        }

        // ---- online softmax (base-2) ----
        float r0 = -1e30f, r1 = -1e30f;
        #pragma unroll
        for (int jb = 0; jb < 8; jb++) {
            r0 = fmaxf(r0, fmaxf(sacc[jb][0], sacc[jb][1]));
            r1 = fmaxf(r1, fmaxf(sacc[jb][2], sacc[jb][3]));
        }
        r0 = fmaxf(r0, __shfl_xor_sync(0xffffffffu, r0, 1));
        r0 = fmaxf(r0, __shfl_xor_sync(0xffffffffu, r0, 2));
        r1 = fmaxf(r1, __shfl_xor_sync(0xffffffffu, r1, 1));
        r1 = fmaxf(r1, __shfl_xor_sync(0xffffffffu, r1, 2));

        const float mn0 = fmaxf(m0, r0), mn1 = fmaxf(m1, r1);
        const float cr0 = exp2f(m0 - mn0), cr1 = exp2f(m1 - mn1);
        m0 = mn0; m1 = mn1;
        l0 *= cr0; l1 *= cr1;
        #pragma unroll
        for (int db = 0; db < 8; db++) {
            o[db][0] *= cr0; o[db][1] *= cr0;
            o[db][2] *= cr1; o[db][3] *= cr1;
        }

        // P = 2^(S - m) packed directly into A-fragments (FA2 layout identity)
        uint32_t pf[4][4];
        #pragma unroll
        for (int jb = 0; jb < 8; jb++) {
            float p0 = exp2f(sacc[jb][0] - m0);
            float p1 = exp2f(sacc[jb][1] - m0);
            float p2 = exp2f(sacc[jb][2] - m1);
            float p3 = exp2f(sacc[jb][3] - m1);
            l0 += p0 + p1; l1 += p2 + p3;
            const int kc = jb >> 1;
            const int hh = (jb & 1) * 2;
            pf[kc][hh]     = packh2(p0, p1);
            pf[kc][hh + 1] = packh2(p2, p3);
        }

        // ---- O += P V ----
        #pragma unroll
        for (int dn = 0; dn < 8; dn++) {
            uint32_t v1[4], v2[4];
            ldm_x4_t(v1, vb + (uint32_t)lane * 144 + dn * 16);
            ldm_x4_t(v2, vb + (uint32_t)(32 + lane) * 144 + dn * 16);
            mma_f16(o[dn], pf[0], &v1[0]);
            mma_f16(o[dn], pf[1], &v1[2]);
            mma_f16(o[dn], pf[2], &v2[0]);
            mma_f16(o[dn], pf[3], &v2[2]);
        }
        if (kt < qb) __syncthreads();   // guard buffer refill (none after last tile)
    }

    l0 += __shfl_xor_sync(0xffffffffu, l0, 1);
    l0 += __shfl_xor_sync(0xffffffffu, l0, 2);
    l1 += __shfl_xor_sync(0xffffffffu, l1, 1);
    l1 += __shfl_xor_sync(0xffffffffu, l1, 2);
    const float inv0 = 1.0f / l0, inv1 = 1.0f / l1;

    const int bi = bh >> 4, hi = bh & 15;
    const int q0 = qb * 64 + wid * 16 + qr;
    const int q1 = q0 + 8;
    __half* y0 = Y + ((size_t)(bi * T + q0)) * C + hi * Dd;
    __half* y1 = Y + ((size_t)(bi * T + q1)) * C + hi * Dd;
    #pragma unroll
    for (int dn = 0; dn < 8; dn++) {
        const int d = dn * 8 + 2 * qc;
        *(__half2*)&y0[d] = __floats2half2_rn(o[dn][0] * inv0, o[dn][1] * inv0);
        *(__half2*)&y1[d] = __floats2half2_rn(o[dn][2] * inv1, o[dn][3] * inv1);
    }
}

// ---------------- QKV weight transpose -> fp16 [N][K] (+ bias pack) ----------
__global__ void transpose_qkv(const float* __restrict__ wq, const float* __restrict__ wk,
                              const float* __restrict__ wv,
                              __half* __restrict__ oq, __half* __restrict__ ok,
                              __half* __restrict__ ov,
                              const float* __restrict__ bq, const float* __restrict__ bk,
                              const float* __restrict__ bv, float* __restrict__ bqkv)
{
    __shared__ float tile[32][33];
    const int z = blockIdx.z;
    const float* in = (z == 0) ? wq : (z == 1) ? wk : wv;
    __half* out = (z == 0) ? oq : (z == 1) ? ok : ov;
    int x = blockIdx.x * 32 + threadIdx.x;
    int y = blockIdx.y * 32 + threadIdx.y;
    #pragma unroll
    for (int j = 0; j < 32; j += 8)
        tile[threadIdx.y + j][threadIdx.x] = in[(size_t)(y + j) * C + x];
    __syncthreads();
    int xo = blockIdx.y * 32 + threadIdx.x;
    int yo = blockIdx.x * 32 + threadIdx.y;
    #pragma unroll
    for (int j = 0; j < 32; j += 8)
        out[(size_t)(yo + j) * C + xo] = __float2half_rn(tile[threadIdx.x][threadIdx.y + j]);

    if (z == 2 && blockIdx.x == 0 && blockIdx.y == 0) {
        int t = threadIdx.y * 32 + threadIdx.x;
        for (int i = t; i < 3 * C; i += 256) {
            const float* src = (i < C) ? bq : (i < 2 * C) ? bk : bv;
            bqkv[i] = src[i & (C - 1)];
        }
    }
}

__global__ void transpose_h(const float* __restrict__ in, __half* __restrict__ out,
                            int R, int Cc)
{
    __shared__ float tile[32][33];
    int x = blockIdx.x * 32 + threadIdx.x;
    int y = blockIdx.y * 32 + threadIdx.y;
    #pragma unroll
    for (int j = 0; j < 32; j += 8)
        tile[threadIdx.y + j][threadIdx.x] = in[(size_t)(y + j) * Cc + x];
    __syncthreads();
    int xo = blockIdx.y * 32 + threadIdx.x;
    int yo = blockIdx.x * 32 + threadIdx.y;
    #pragma unroll
    for (int j = 0; j < 32; j += 8)
        out[(size_t)(yo + j) * R + xo] = __float2half_rn(tile[threadIdx.x][threadIdx.y + j]);
}

// ---------------- LayerNorm: warp-per-row, fp16 row cache (low regs) ---------
__global__ __launch_bounds__(512)
void ln_kernel(const float* __restrict__ X,
               const float* __restrict__ w,
               const float* __restrict__ b,
               __half* __restrict__ out)
{
    const int lane = threadIdx.x & 31;
    const int row  = blockIdx.x * 16 + (threadIdx.x >> 5);
    const float* xr = X + (size_t)row * C;

    __half2 xh[16];
    float s = 0.0f, sq = 0.0f;
    #pragma unroll
    for (int i = 0; i < 8; i++) {
        const float4 v = *(const float4*)&xr[(i * 32 + lane) * 4];
        s  += v.x + v.y + v.z + v.w;
        sq += v.x*v.x + v.y*v.y + v.z*v.z + v.w*v.w;
        xh[2*i]     = __floats2half2_rn(v.x, v.y);
        xh[2*i + 1] = __floats2half2_rn(v.z, v.w);
    }
    #pragma unroll
    for (int off = 16; off > 0; off >>= 1) {
        s  += __shfl_xor_sync(0xffffffffu, s,  off);
        sq += __shfl_xor_sync(0xffffffffu, sq, off);
    }
    const float mu = s * (1.0f / C);
    const float r  = rsqrtf(sq * (1.0f / C) - mu * mu + 1e-5f);

    __half* orow = out + (size_t)row * C;
    #pragma unroll
    for (int i = 0; i < 8; i++) {
        const int c = (i * 32 + lane) * 4;
        const float4 wv = *(const float4*)&w[c];
        const float4 bv = *(const float4*)&b[c];
        const float2 a0 = __half22float2(xh[2*i]);
        const float2 a1 = __half22float2(xh[2*i + 1]);
        __half2 h0 = __floats2half2_rn((a0.x - mu) * r * wv.x + bv.x,
                                       (a0.y - mu) * r * wv.y + bv.y);
        __half2 h1 = __floats2half2_rn((a1.x - mu) * r * wv.z + bv.z,
                                       (a1.y - mu) * r * wv.w + bv.w);
        *(__half2*)&orow[c]     = h0;
        *(__half2*)&orow[c + 2] = h1;
    }
}

// ---------------- launcher ----------------------------------------------------
extern "C" void kernel_launch(void* const* d_in, const int* in_sizes, int n_in,
                              void* d_out, int out_size)
{
    const float* x     = (const float*)d_in[0];
    const float* ln1_w = (const float*)d_in[1];
    const float* ln1_b = (const float*)d_in[2];
    const float* wq    = (const float*)d_in[3];
    const float* bq    = (const float*)d_in[4];
    const float* wk    = (const float*)d_in[5];
    const float* bk    = (const float*)d_in[6];
    const float* wv    = (const float*)d_in[7];
    const float* bv    = (const float*)d_in[8];
    const float* wo    = (const float*)d_in[9];
    const float* bo    = (const float*)d_in[10];
    const float* ln2_w = (const float*)d_in[11];
    const float* ln2_b = (const float*)d_in[12];
    const float* w1    = (const float*)d_in[13];
    const float* b1    = (const float*)d_in[14];
    const float* w2    = (const float*)d_in[15];
    const float* b2    = (const float*)d_in[16];

    __half *h, *qkv, *y, *hid, *wtqkv, *wto, *wt1, *wt2;
    float *x1, *bqkv;
    cudaGetSymbolAddress((void**)&h,     g_h);
    cudaGetSymbolAddress((void**)&qkv,   g_qkv);
    cudaGetSymbolAddress((void**)&y,     g_y);
    cudaGetSymbolAddress((void**)&x1,    g_x1);
    cudaGetSymbolAddress((void**)&hid,   g_hid);
    cudaGetSymbolAddress((void**)&wtqkv, g_wtqkv);
    cudaGetSymbolAddress((void**)&bqkv,  g_bqkv);
    cudaGetSymbolAddress((void**)&wto,   g_wto);
    cudaGetSymbolAddress((void**)&wt1,   g_wt1);
    cudaGetSymbolAddress((void**)&wt2,   g_wt2);

    float* out = (float*)d_out;
    __half* q = qkv;
    __half* k = qkv + (size_t)M * C;
    __half* v = qkv + (size_t)2 * M * C;

    cudaFuncSetAttribute(gemm_mma<0>, cudaFuncAttributeMaxDynamicSharedMemorySize, SMEM_G);
    cudaFuncSetAttribute(gemm_mma<1>, cudaFuncAttributeMaxDynamicSharedMemorySize, SMEM_G);
    cudaFuncSetAttribute(gemm_mma<2>, cudaFuncAttributeMaxDynamicSharedMemorySize, SMEM_G);
    cudaFuncSetAttribute(attn_mma,    cudaFuncAttributeMaxDynamicSharedMemorySize, SMEM_ATT);

    // fork low-priority side stream for weight prep
    cudaEventRecord(g_ps.e0, 0);
    cudaStreamWaitEvent(g_ps.s1, g_ps.e0, 0);

    dim3 tb(32, 8);
    // e1 gates ONLY what the QKV GEMM needs (wq/wk/wv + bias)
    transpose_qkv<<<dim3(C/32, C/32, 3), tb, 0, g_ps.s1>>>(
        wq, wk, wv, wtqkv, wtqkv + C * C, wtqkv + 2 * C * C, bq, bk, bv, bqkv);
    cudaEventRecord(g_ps.e1, g_ps.s1);
    // wo/w1/w2 finish during the QKV GEMM; gated by e2 before attention
    transpose_h<<<dim3(C/32,  C/32),  tb, 0, g_ps.s1>>>(wo, wto, C,  C);
    transpose_h<<<dim3(FF/32, C/32),  tb, 0, g_ps.s1>>>(w1, wt1, C,  FF);
    transpose_h<<<dim3(C/32,  FF/32), tb, 0, g_ps.s1>>>(w2, wt2, FF, C);
    cudaEventRecord(g_ps.e2, g_ps.s1);

    // main stream: LN1 overlaps qkv transpose
    ln_kernel<<<M / 16, 512>>>(x, ln1_w, ln1_b, h);
    cudaStreamWaitEvent(0, g_ps.e1, 0);          // need wtqkv + bqkv
    gemm_mma<0><<<dim3(3*C/128, M/128), 256, SMEM_G>>>(h, wtqkv, bqkv, nullptr, qkv, 3*C, C);
    cudaStreamWaitEvent(0, g_ps.e2, 0);          // wto/w1/w2 ready (free wait here)
    attn_mma<<<dim3(T/64, Bb*Hh), 128, SMEM_ATT>>>(q, k, v, y);
    gemm_mma<1><<<dim3(C/128,  M/128), 256, SMEM_G>>>(y, wto, bo, x, x1, C, C);
    ln_kernel<<<M / 16, 512>>>(x1, ln2_w, ln2_b, h);
    gemm_mma<2><<<dim3(FF/128, M/128), 256, SMEM_G>>>(h, wt1, b1, nullptr, hid, FF, C);
    gemm_mma<1><<<dim3(C/128,  M/128), 256, SMEM_G>>>(hid, wt2, b2, x1, out, C, FF);
}